// round 1
// baseline (speedup 1.0000x reference)
#include <cuda_runtime.h>
#include <math.h>

#define CIN   64
#define COUT  64
#define Hdim  96
#define Wdim  96
#define Bdim  8
#define Kk    9
#define HW    (Hdim*Wdim)     /* 9216  */
#define PTOT  (Bdim*HW)       /* 73728 */

// Scratch (no cudaMalloc allowed)
__device__ float g_xt [Bdim*HW*CIN];    // NHWC transposed x: [(b*HW + h*96 + w)*64 + c]
__device__ float g_pos[PTOT*Kk*3];      // per (pixel,k): ys, xs, mask(sigmoid applied)

// ---------------------------------------------------------------------------
// Kernel A: NCHW -> NHWC transpose of x
// ---------------------------------------------------------------------------
__global__ __launch_bounds__(256) void dc_transpose(const float* __restrict__ x)
{
    __shared__ float tile[64*65];
    int b  = blockIdx.x / 144;
    int s0 = (blockIdx.x % 144) * 64;
    const float* xb = x + (size_t)b * CIN * HW;
    for (int i = threadIdx.x; i < 64*64; i += 256) {
        int c = i >> 6, s = i & 63;
        tile[c*65 + s] = xb[(size_t)c*HW + s0 + s];
    }
    __syncthreads();
    float* xtb = g_xt + ((size_t)b*HW + s0) * 64;
    for (int i = threadIdx.x; i < 64*64; i += 256) {
        int s = i >> 6, c = i & 63;
        xtb[s*64 + c] = tile[c*65 + s];
    }
}

// ---------------------------------------------------------------------------
// Kernel B: offset conv (27 out-ch, 3x3) + transform to (ys, xs, mask)
// Block: 32 pixels (one third of a row) x 256 threads
// ---------------------------------------------------------------------------
#define B_SP_OFF   0                    // patch: 3 rows x 34 cols x 68 (pad) floats
#define B_SP_SIZE  (3*34*68)            // 6936
#define B_SW_OFF   (B_SP_OFF + B_SP_SIZE)
#define B_SW_SIZE  (9*27*68)            // 16524 : sWo[(kk*27+m)*68 + c]
#define B_OM_OFF   (B_SW_OFF + B_SW_SIZE)
#define B_OM_SIZE  (32*28)              // om staging
#define B_SMEM_FLOATS (B_OM_OFF + B_OM_SIZE)

__global__ __launch_bounds__(256) void dc_offsets(const float* __restrict__ w_off,
                                                  const float* __restrict__ b_off)
{
    extern __shared__ float sm[];
    float* sP  = sm + B_SP_OFF;
    float* sWo = sm + B_SW_OFF;
    float* sOm = sm + B_OM_OFF;

    int tid  = threadIdx.x;
    int tile = blockIdx.x * 32;       // global pixel index of first pixel
    int b    = tile / HW;
    int rem  = tile % HW;
    int h    = rem / Wdim;
    int w0   = rem % Wdim;            // 0, 32, or 64

    // Load 3-row input patch (NHWC), cols w0-1 .. w0+32, zero-padded OOB
    const float* xtb = g_xt + (size_t)b * HW * 64;
    for (int r = 0; r < 3; r++) {
        int hh = h - 1 + r;
        bool rv = (hh >= 0) & (hh < Hdim);
        for (int i = tid; i < 34*64; i += 256) {
            int col = i >> 6, c = i & 63;
            int ww = w0 - 1 + col;
            float v = 0.f;
            if (rv && ww >= 0 && ww < Wdim)
                v = xtb[((size_t)hh*Wdim + ww)*64 + c];
            sP[(r*34 + col)*68 + c] = v;
        }
    }
    // Load + re-layout offset weights: global [m][c][ky][kx] -> sWo[(kk*27+m)*68 + c]
    for (int i = tid; i < 27*64*9; i += 256) {
        int m = i / 576, rr = i % 576;
        int c = rr / 9,  kk = rr % 9;
        sWo[(kk*27 + m)*68 + c] = w_off[i];
    }
    __syncthreads();

    int px = tid >> 3;     // 0..31
    int j  = tid & 7;      // 0..7 ; m in {j, j+8, j+16, (j+24 if j<3)}
    float acc0 = 0.f, acc1 = 0.f, acc2 = 0.f, acc3 = 0.f;
    int m3row = (j < 3) ? (j + 24) : 0;   // safe row for j>=3 (result discarded)

    #pragma unroll
    for (int kk = 0; kk < 9; kk++) {
        int ky = kk / 3, kx = kk % 3;
        const float4* xp = (const float4*)&sP[(ky*34 + px + kx)*68];
        const float4* wp0 = (const float4*)&sWo[(kk*27 + j     )*68];
        const float4* wp1 = (const float4*)&sWo[(kk*27 + j + 8 )*68];
        const float4* wp2 = (const float4*)&sWo[(kk*27 + j + 16)*68];
        const float4* wp3 = (const float4*)&sWo[(kk*27 + m3row )*68];
        #pragma unroll
        for (int c4 = 0; c4 < 16; c4++) {
            float4 xv = xp[c4];
            float4 w;
            w = wp0[c4]; acc0 += xv.x*w.x + xv.y*w.y + xv.z*w.z + xv.w*w.w;
            w = wp1[c4]; acc1 += xv.x*w.x + xv.y*w.y + xv.z*w.z + xv.w*w.w;
            w = wp2[c4]; acc2 += xv.x*w.x + xv.y*w.y + xv.z*w.z + xv.w*w.w;
            w = wp3[c4]; acc3 += xv.x*w.x + xv.y*w.y + xv.z*w.z + xv.w*w.w;
        }
    }
    __syncthreads();
    sOm[px*28 + j     ] = acc0 + b_off[j];
    sOm[px*28 + j + 8 ] = acc1 + b_off[j + 8];
    sOm[px*28 + j + 16] = acc2 + b_off[j + 16];
    if (j < 3) sOm[px*28 + j + 24] = acc3 + b_off[j + 24];
    __syncthreads();

    // Transform to (ys, xs, mask) and store
    for (int idx = tid; idx < 32*9; idx += 256) {
        int p2 = idx / 9, k = idx % 9;
        float dy = sOm[p2*28 + 2*k];
        float dx = sOm[p2*28 + 2*k + 1];
        float mv = sOm[p2*28 + 18 + k];
        float mask = 1.0f / (1.0f + __expf(-mv));
        int ky = k / 3, kx = k % 3;
        float ys = (float)(h - 1 + ky) + dy;
        float xs = (float)(w0 + p2 - 1 + kx) + dx;
        float* gp = g_pos + (size_t)(tile + p2)*27 + k*3;
        gp[0] = ys; gp[1] = xs; gp[2] = mask;
    }
}

// ---------------------------------------------------------------------------
// Kernel C: fused bilinear sample + mask + 96x64x576 GEMM + bias, per (b,h) row
// 384 threads = 96 pixels x 4 threads (j), each thread: 16 output channels
//   o = 16*t + 4*j + u,  t,u in 0..3
// ---------------------------------------------------------------------------
#define C_SW_SIZE   (9*64*64)     // 36864 : sW[(k*64+c)*64 + o]
#define C_SS_SIZE   (96*68)       // 6528  : sS[px*68 + c] (padded stride)
#define C_SP_SIZE   (96*27)       // 2592  : positions
#define C_SMEM_FLOATS (C_SW_SIZE + C_SS_SIZE + C_SP_SIZE)

__global__ __launch_bounds__(384,1) void dc_main(const float* __restrict__ weight,
                                                 const float* __restrict__ bias,
                                                 float* __restrict__ out)
{
    extern __shared__ float sm[];
    float* sW   = sm;
    float* sS   = sm + C_SW_SIZE;
    float* sPos = sS + C_SS_SIZE;

    int tid = threadIdx.x;
    int b = blockIdx.x / Hdim;
    int h = blockIdx.x % Hdim;

    // Weights: global [o][c][k] -> sW[(k*64+c)*64 + o]
    for (int i = tid; i < 36864; i += 384) {
        int o = i / 576, r = i % 576, c = r / 9, k = r % 9;
        sW[(k*64 + c)*64 + o] = weight[i];
    }
    // Positions for this row (contiguous)
    const float* gp = g_pos + (size_t)(b*HW + h*Wdim)*27;
    for (int i = tid; i < 96*27; i += 384) sPos[i] = gp[i];

    int px = tid >> 2;   // 0..95
    int j  = tid & 3;    // 0..3

    float acc[16];
    #pragma unroll
    for (int t = 0; t < 4; t++)
        #pragma unroll
        for (int u = 0; u < 4; u++)
            acc[t*4 + u] = bias[16*t + 4*j + u];

    const float* xtb = g_xt + (size_t)b * HW * 64;

    for (int k = 0; k < 9; k++) {
        __syncthreads();   // sS from previous iteration fully consumed
        // ---- gather phase: this thread loads c = 16j .. 16j+15 for its pixel
        float ys = sPos[px*27 + k*3 + 0];
        float xs = sPos[px*27 + k*3 + 1];
        float mk = sPos[px*27 + k*3 + 2];
        float y0f = floorf(ys), x0f = floorf(xs);
        float ty = ys - y0f,  tx = xs - x0f;
        int iy0 = (int)y0f, ix0 = (int)x0f;
        int iy1 = iy0 + 1,  ix1 = ix0 + 1;
        bool vy0 = (iy0 >= 0) & (iy0 < Hdim);
        bool vy1 = (iy1 >= 0) & (iy1 < Hdim);
        bool vx0 = (ix0 >= 0) & (ix0 < Wdim);
        bool vx1 = (ix1 >= 0) & (ix1 < Wdim);
        float m00 = (vy0 & vx0) ? (1.f-ty)*(1.f-tx)*mk : 0.f;
        float m01 = (vy0 & vx1) ? (1.f-ty)*tx      *mk : 0.f;
        float m10 = (vy1 & vx0) ? ty      *(1.f-tx)*mk : 0.f;
        float m11 = (vy1 & vx1) ? ty      *tx      *mk : 0.f;
        int cy0 = min(max(iy0,0),Hdim-1), cy1 = min(max(iy1,0),Hdim-1);
        int cx0 = min(max(ix0,0),Wdim-1), cx1 = min(max(ix1,0),Wdim-1);
        const float4* p00 = (const float4*)(xtb + ((size_t)cy0*Wdim + cx0)*64);
        const float4* p01 = (const float4*)(xtb + ((size_t)cy0*Wdim + cx1)*64);
        const float4* p10 = (const float4*)(xtb + ((size_t)cy1*Wdim + cx0)*64);
        const float4* p11 = (const float4*)(xtb + ((size_t)cy1*Wdim + cx1)*64);
        float4* srow = (float4*)&sS[px*68];
        #pragma unroll
        for (int u = 0; u < 4; u++) {
            int q = j*4 + u;
            float4 a = p00[q], bb = p01[q], cc = p10[q], dd = p11[q];
            float4 s;
            s.x = m00*a.x + m01*bb.x + m10*cc.x + m11*dd.x;
            s.y = m00*a.y + m01*bb.y + m10*cc.y + m11*dd.y;
            s.z = m00*a.z + m01*bb.z + m10*cc.z + m11*dd.z;
            s.w = m00*a.w + m01*bb.w + m10*cc.w + m11*dd.w;
            srow[q] = s;
        }
        __syncthreads();
        // ---- GEMM phase: acc[o] += sum_c sS[px][c] * sW[k][c][o]
        const float* wk = sW + k*4096;
        const float4* xrow = (const float4*)&sS[px*68];
        #pragma unroll
        for (int c4 = 0; c4 < 16; c4++) {
            float4 xv = xrow[c4];
            #pragma unroll
            for (int t = 0; t < 4; t++) {
                const float* wb = wk + (c4*4)*64 + 16*t + 4*j;
                float4 w0 = *(const float4*)(wb);
                float4 w1 = *(const float4*)(wb + 64);
                float4 w2 = *(const float4*)(wb + 128);
                float4 w3 = *(const float4*)(wb + 192);
                acc[t*4+0] += xv.x*w0.x + xv.y*w1.x + xv.z*w2.x + xv.w*w3.x;
                acc[t*4+1] += xv.x*w0.y + xv.y*w1.y + xv.z*w2.y + xv.w*w3.y;
                acc[t*4+2] += xv.x*w0.z + xv.y*w1.z + xv.z*w2.z + xv.w*w3.z;
                acc[t*4+3] += xv.x*w0.w + xv.y*w1.w + xv.z*w2.w + xv.w*w3.w;
            }
        }
    }

    // ---- epilogue: stage through SMEM for coalesced NCHW stores
    __syncthreads();
    float* sOut = sW;   // reuse (accs are in registers)
    #pragma unroll
    for (int t = 0; t < 4; t++)
        #pragma unroll
        for (int u = 0; u < 4; u++) {
            int o = 16*t + 4*j + u;
            sOut[o*96 + px] = acc[t*4 + u];
        }
    __syncthreads();
    float* ob = out + (size_t)b*COUT*HW + h*Wdim;
    for (int i = tid; i < COUT*96; i += 384) {
        int o = i / 96, p = i % 96;
        ob[(size_t)o*HW + p] = sOut[i];
    }
}

// ---------------------------------------------------------------------------
extern "C" void kernel_launch(void* const* d_in, const int* in_sizes, int n_in,
                              void* d_out, int out_size)
{
    const float* x      = (const float*)d_in[0];
    const float* w_off  = (const float*)d_in[1];
    const float* b_off  = (const float*)d_in[2];
    const float* weight = (const float*)d_in[3];
    const float* bias   = (const float*)d_in[4];
    float* out = (float*)d_out;

    static bool attr_done = false;
    if (!attr_done) {
        cudaFuncSetAttribute(dc_offsets, cudaFuncAttributeMaxDynamicSharedMemorySize,
                             B_SMEM_FLOATS * (int)sizeof(float));
        cudaFuncSetAttribute(dc_main, cudaFuncAttributeMaxDynamicSharedMemorySize,
                             C_SMEM_FLOATS * (int)sizeof(float));
        attr_done = true;
    }

    dc_transpose<<<Bdim * (HW/64), 256>>>(x);
    dc_offsets  <<<PTOT/32, 256, B_SMEM_FLOATS * sizeof(float)>>>(w_off, b_off);
    dc_main     <<<Bdim * Hdim, 384, C_SMEM_FLOATS * sizeof(float)>>>(weight, bias, out);
}

// round 2
// speedup vs baseline: 1.1151x; 1.1151x over previous
#include <cuda_runtime.h>
#include <math.h>

#define CIN   64
#define COUT  64
#define Hdim  96
#define Wdim  96
#define Bdim  8
#define HW    (Hdim*Wdim)     /* 9216  */
#define PTOT  (Bdim*HW)       /* 73728 */

typedef unsigned long long u64;

// Scratch (no cudaMalloc allowed)
__device__ float g_xt [Bdim*HW*CIN];     // NHWC x: [(b*HW + h*96 + w)*64 + c]
__device__ float g_pos[PTOT*9*3];        // per (pixel,k): ys, xs, mask
__device__ float g_wt [9*64*64];         // weights re-laid: [k][c][o]

// ---------------- packed f32x2 helpers -----------------------------------
__device__ __forceinline__ u64 pack2(float lo, float hi) {
    u64 r; asm("mov.b64 %0, {%1,%2};" : "=l"(r) : "f"(lo), "f"(hi)); return r;
}
__device__ __forceinline__ void unpack2(u64 v, float& lo, float& hi) {
    asm("mov.b64 {%0,%1}, %2;" : "=f"(lo), "=f"(hi) : "l"(v));
}
__device__ __forceinline__ u64 ffma2(u64 a, u64 b, u64 c) {
    u64 d; asm("fma.rn.f32x2 %0, %1, %2, %3;" : "=l"(d) : "l"(a), "l"(b), "l"(c));
    return d;
}
__device__ __forceinline__ void lds_v2u64(u64& a, u64& b, unsigned addr) {
    asm volatile("ld.shared.v2.u64 {%0,%1}, [%2];" : "=l"(a), "=l"(b) : "r"(addr));
}
__device__ __forceinline__ void cp_async16(unsigned saddr, const void* g) {
    asm volatile("cp.async.cg.shared.global [%0], [%1], 16;" :: "r"(saddr), "l"(g));
}
__device__ __forceinline__ void cp_commit() { asm volatile("cp.async.commit_group;"); }
__device__ __forceinline__ void cp_wait0()  { asm volatile("cp.async.wait_group 0;"); }

// ---------------------------------------------------------------------------
// Kernel A: NCHW -> NHWC transpose of x
// ---------------------------------------------------------------------------
__global__ __launch_bounds__(256) void dc_transpose(const float* __restrict__ x)
{
    __shared__ float tile[64*65];
    int b  = blockIdx.x / 144;
    int s0 = (blockIdx.x % 144) * 64;
    const float* xb = x + (size_t)b * CIN * HW;
    for (int i = threadIdx.x; i < 64*64; i += 256) {
        int c = i >> 6, s = i & 63;
        tile[c*65 + s] = xb[(size_t)c*HW + s0 + s];
    }
    __syncthreads();
    float* xtb = g_xt + ((size_t)b*HW + s0) * 64;
    for (int i = threadIdx.x; i < 64*64; i += 256) {
        int s = i >> 6, c = i & 63;
        xtb[s*64 + c] = tile[c*65 + s];
    }
}

// ---------------------------------------------------------------------------
// Kernel A2: weight [o][c][k] -> g_wt[k][c][o]
// ---------------------------------------------------------------------------
__global__ __launch_bounds__(256) void dc_wtrans(const float* __restrict__ w)
{
    int i = blockIdx.x * 256 + threadIdx.x;
    if (i < 9*64*64) {
        int o = i / 576, r = i % 576, c = r / 9, k = r % 9;
        g_wt[k*4096 + c*64 + o] = w[i];
    }
}

// ---------------------------------------------------------------------------
// Kernel B: offset conv (27 out-ch, 3x3) + transform to (ys, xs, mask)
// ---------------------------------------------------------------------------
#define B_SP_OFF   0
#define B_SP_SIZE  (3*34*68)
#define B_SW_OFF   (B_SP_OFF + B_SP_SIZE)
#define B_SW_SIZE  (9*27*68)
#define B_OM_OFF   (B_SW_OFF + B_SW_SIZE)
#define B_OM_SIZE  (32*28)
#define B_SMEM_FLOATS (B_OM_OFF + B_OM_SIZE)

__global__ __launch_bounds__(256) void dc_offsets(const float* __restrict__ w_off,
                                                  const float* __restrict__ b_off)
{
    extern __shared__ float sm[];
    float* sP  = sm + B_SP_OFF;
    float* sWo = sm + B_SW_OFF;
    float* sOm = sm + B_OM_OFF;

    int tid  = threadIdx.x;
    int tile = blockIdx.x * 32;
    int b    = tile / HW;
    int rem  = tile % HW;
    int h    = rem / Wdim;
    int w0   = rem % Wdim;

    const float* xtb = g_xt + (size_t)b * HW * 64;
    for (int r = 0; r < 3; r++) {
        int hh = h - 1 + r;
        bool rv = (hh >= 0) & (hh < Hdim);
        for (int i = tid; i < 34*64; i += 256) {
            int col = i >> 6, c = i & 63;
            int ww = w0 - 1 + col;
            float v = 0.f;
            if (rv && ww >= 0 && ww < Wdim)
                v = xtb[((size_t)hh*Wdim + ww)*64 + c];
            sP[(r*34 + col)*68 + c] = v;
        }
    }
    for (int i = tid; i < 27*64*9; i += 256) {
        int m = i / 576, rr = i % 576;
        int c = rr / 9,  kk = rr % 9;
        sWo[(kk*27 + m)*68 + c] = w_off[i];
    }
    __syncthreads();

    int px = tid >> 3;
    int j  = tid & 7;
    float acc0 = 0.f, acc1 = 0.f, acc2 = 0.f, acc3 = 0.f;
    int m3row = (j < 3) ? (j + 24) : 0;

    #pragma unroll
    for (int kk = 0; kk < 9; kk++) {
        int ky = kk / 3, kx = kk % 3;
        const float4* xp  = (const float4*)&sP[(ky*34 + px + kx)*68];
        const float4* wp0 = (const float4*)&sWo[(kk*27 + j     )*68];
        const float4* wp1 = (const float4*)&sWo[(kk*27 + j + 8 )*68];
        const float4* wp2 = (const float4*)&sWo[(kk*27 + j + 16)*68];
        const float4* wp3 = (const float4*)&sWo[(kk*27 + m3row )*68];
        #pragma unroll
        for (int c4 = 0; c4 < 16; c4++) {
            float4 xv = xp[c4];
            float4 w;
            w = wp0[c4]; acc0 += xv.x*w.x + xv.y*w.y + xv.z*w.z + xv.w*w.w;
            w = wp1[c4]; acc1 += xv.x*w.x + xv.y*w.y + xv.z*w.z + xv.w*w.w;
            w = wp2[c4]; acc2 += xv.x*w.x + xv.y*w.y + xv.z*w.z + xv.w*w.w;
            w = wp3[c4]; acc3 += xv.x*w.x + xv.y*w.y + xv.z*w.z + xv.w*w.w;
        }
    }
    __syncthreads();
    sOm[px*28 + j     ] = acc0 + b_off[j];
    sOm[px*28 + j + 8 ] = acc1 + b_off[j + 8];
    sOm[px*28 + j + 16] = acc2 + b_off[j + 16];
    if (j < 3) sOm[px*28 + j + 24] = acc3 + b_off[j + 24];
    __syncthreads();

    for (int idx = tid; idx < 32*9; idx += 256) {
        int p2 = idx / 9, k = idx % 9;
        float dy = sOm[p2*28 + 2*k];
        float dx = sOm[p2*28 + 2*k + 1];
        float mv = sOm[p2*28 + 18 + k];
        float mask = 1.0f / (1.0f + __expf(-mv));
        int ky = k / 3, kx = k % 3;
        float ys = (float)(h - 1 + ky) + dy;
        float xs = (float)(w0 + p2 - 1 + kx) + dx;
        float* gp = g_pos + (size_t)(tile + p2)*27 + k*3;
        gp[0] = ys; gp[1] = xs; gp[2] = mask;
    }
}

// ---------------------------------------------------------------------------
// Kernel C: fused sample + GEMM.  Block = 128 consecutive pixels of one image.
// 256 threads. GEMM: thread = (pp = tid>>2) x (j = tid&3); pixels pp, pp+64;
// 16 outputs o = j*16..j*16+15, packed f32x2 accumulators.
// smem (floats): sW double buf 2x4096, sS double buf 2x(128*68)
// ---------------------------------------------------------------------------
#define C_SW0   0
#define C_SW1   4096
#define C_SS0   8192
#define C_SS1   (8192 + 128*68)
#define C_SMEM_FLOATS (8192 + 2*128*68)   /* 25600 floats = 100 KB */

__device__ __forceinline__ void dc_gather(const float* __restrict__ xtb,
                                          int gpixBase, int px, int half,
                                          int k, float* __restrict__ dst)
{
    const float* pp = g_pos + (size_t)(gpixBase + px)*27 + k*3;
    float ys = pp[0], xs = pp[1], mk = pp[2];
    float y0f = floorf(ys), x0f = floorf(xs);
    float ty = ys - y0f, tx = xs - x0f;
    int iy0 = (int)y0f, ix0 = (int)x0f;
    int iy1 = iy0 + 1,  ix1 = ix0 + 1;
    bool vy0 = (iy0 >= 0) & (iy0 < Hdim);
    bool vy1 = (iy1 >= 0) & (iy1 < Hdim);
    bool vx0 = (ix0 >= 0) & (ix0 < Wdim);
    bool vx1 = (ix1 >= 0) & (ix1 < Wdim);
    float m00 = (vy0 & vx0) ? (1.f-ty)*(1.f-tx)*mk : 0.f;
    float m01 = (vy0 & vx1) ? (1.f-ty)*tx      *mk : 0.f;
    float m10 = (vy1 & vx0) ? ty      *(1.f-tx)*mk : 0.f;
    float m11 = (vy1 & vx1) ? ty      *tx      *mk : 0.f;
    int cy0 = min(max(iy0,0),Hdim-1), cy1 = min(max(iy1,0),Hdim-1);
    int cx0 = min(max(ix0,0),Wdim-1), cx1 = min(max(ix1,0),Wdim-1);
    const float4* p00 = (const float4*)(xtb + ((size_t)cy0*Wdim + cx0)*64);
    const float4* p01 = (const float4*)(xtb + ((size_t)cy0*Wdim + cx1)*64);
    const float4* p10 = (const float4*)(xtb + ((size_t)cy1*Wdim + cx0)*64);
    const float4* p11 = (const float4*)(xtb + ((size_t)cy1*Wdim + cx1)*64);
    float4* d4 = (float4*)dst;
    #pragma unroll
    for (int u = 0; u < 8; u++) {
        int q = half*8 + u;
        float4 a = p00[q], bb = p01[q], cc = p10[q], dd = p11[q];
        float4 s;
        s.x = m00*a.x + m01*bb.x + m10*cc.x + m11*dd.x;
        s.y = m00*a.y + m01*bb.y + m10*cc.y + m11*dd.y;
        s.z = m00*a.z + m01*bb.z + m10*cc.z + m11*dd.z;
        s.w = m00*a.w + m01*bb.w + m10*cc.w + m11*dd.w;
        d4[u] = s;
    }
}

__global__ __launch_bounds__(256, 2) void dc_main(const float* __restrict__ bias,
                                                  float* __restrict__ out)
{
    extern __shared__ float sm[];
    unsigned smBase;
    {
        void* p = sm;
        asm("{ .reg .u64 t; cvta.to.shared.u64 t, %1; cvt.u32.u64 %0, t; }"
            : "=r"(smBase) : "l"(p));
    }

    int tid = threadIdx.x;
    int b     = blockIdx.x / 72;
    int pxBase = (blockIdx.x % 72) * 128;       // pixel offset within image
    int gpixBase = b * HW + pxBase;             // global pixel index
    const float* xtb = g_xt + (size_t)b * HW * 64;

    // gather thread mapping
    int gpx  = tid >> 1;
    int ghalf = tid & 1;
    // GEMM thread mapping
    int pp = tid >> 2;          // 0..63
    int j  = tid & 3;           // o-group of 16
    int pxA = pp, pxB = pp + 64;

    // accumulators: 8 o-pairs per pixel
    u64 accA[8], accB[8];
    #pragma unroll
    for (int i = 0; i < 8; i++) {
        float b0 = __ldg(&bias[j*16 + 2*i]);
        float b1 = __ldg(&bias[j*16 + 2*i + 1]);
        accA[i] = pack2(b0, b1);
        accB[i] = pack2(b0, b1);
    }

    // ---- prologue: weights k=0 via cp.async, gather k=0
    {
        unsigned dstW = smBase + (unsigned)(C_SW0 + tid*16) * 4u;
        const float* srcW = g_wt + 0*4096 + tid*16;
        #pragma unroll
        for (int q = 0; q < 4; q++)
            cp_async16(dstW + q*16u, srcW + q*4);
        cp_commit();
        dc_gather(xtb, gpixBase, gpx, ghalf, 0, sm + C_SS0 + gpx*68 + ghalf*32);
        cp_wait0();
    }
    __syncthreads();

    for (int k = 0; k < 9; k++) {
        int cur = k & 1, nxt = cur ^ 1;
        // issue next weight tile (transfers during GEMM)
        if (k < 8) {
            unsigned dstW = smBase + (unsigned)((nxt ? C_SW1 : C_SW0) + tid*16) * 4u;
            const float* srcW = g_wt + (k+1)*4096 + tid*16;
            #pragma unroll
            for (int q = 0; q < 4; q++)
                cp_async16(dstW + q*16u, srcW + q*4);
            cp_commit();
        }

        // ---- GEMM(k): acc[px][o] += sS[px][c] * sW[c][o]
        {
            const float* ss = sm + (cur ? C_SS1 : C_SS0);
            unsigned wB = smBase + (unsigned)((cur ? C_SW1 : C_SW0) + j*16) * 4u;
            #pragma unroll
            for (int c4 = 0; c4 < 16; c4++) {
                float4 xa = *(const float4*)(ss + pxA*68 + c4*4);
                float4 xb = *(const float4*)(ss + pxB*68 + c4*4);
                u64 xaP0 = pack2(xa.x, xa.x), xaP1 = pack2(xa.y, xa.y);
                u64 xaP2 = pack2(xa.z, xa.z), xaP3 = pack2(xa.w, xa.w);
                u64 xbP0 = pack2(xb.x, xb.x), xbP1 = pack2(xb.y, xb.y);
                u64 xbP2 = pack2(xb.z, xb.z), xbP3 = pack2(xb.w, xb.w);
                unsigned wp = wB + (unsigned)(c4*4*64) * 4u;
                #pragma unroll
                for (int cc = 0; cc < 4; cc++) {
                    u64 w0,w1,w2,w3,w4,w5,w6,w7;
                    lds_v2u64(w0, w1, wp);
                    lds_v2u64(w2, w3, wp + 16u);
                    lds_v2u64(w4, w5, wp + 32u);
                    lds_v2u64(w6, w7, wp + 48u);
                    u64 xav = (cc==0)?xaP0:(cc==1)?xaP1:(cc==2)?xaP2:xaP3;
                    u64 xbv = (cc==0)?xbP0:(cc==1)?xbP1:(cc==2)?xbP2:xbP3;
                    accA[0] = ffma2(xav, w0, accA[0]);
                    accA[1] = ffma2(xav, w1, accA[1]);
                    accA[2] = ffma2(xav, w2, accA[2]);
                    accA[3] = ffma2(xav, w3, accA[3]);
                    accA[4] = ffma2(xav, w4, accA[4]);
                    accA[5] = ffma2(xav, w5, accA[5]);
                    accA[6] = ffma2(xav, w6, accA[6]);
                    accA[7] = ffma2(xav, w7, accA[7]);
                    accB[0] = ffma2(xbv, w0, accB[0]);
                    accB[1] = ffma2(xbv, w1, accB[1]);
                    accB[2] = ffma2(xbv, w2, accB[2]);
                    accB[3] = ffma2(xbv, w3, accB[3]);
                    accB[4] = ffma2(xbv, w4, accB[4]);
                    accB[5] = ffma2(xbv, w5, accB[5]);
                    accB[6] = ffma2(xbv, w6, accB[6]);
                    accB[7] = ffma2(xbv, w7, accB[7]);
                    wp += 256u;
                }
            }
        }

        // ---- gather(k+1) into the other sample buffer
        if (k < 8) {
            dc_gather(xtb, gpixBase, gpx, ghalf, k+1,
                      sm + (nxt ? C_SS1 : C_SS0) + gpx*68 + ghalf*32);
            cp_wait0();
        }
        __syncthreads();
    }

    // ---- epilogue: stage [o][px] in smem, coalesced NCHW store
    float* sOut = sm + C_SS0;    // 64*128 = 8192 floats, fits buffer 0
    #pragma unroll
    for (int i = 0; i < 8; i++) {
        int o = j*16 + 2*i;
        float lo, hi;
        unpack2(accA[i], lo, hi);
        sOut[o*128 + pxA] = lo;  sOut[(o+1)*128 + pxA] = hi;
        unpack2(accB[i], lo, hi);
        sOut[o*128 + pxB] = lo;  sOut[(o+1)*128 + pxB] = hi;
    }
    __syncthreads();
    float* ob = out + (size_t)b * COUT * HW + pxBase;
    for (int i = tid; i < 64*128; i += 256) {
        int o = i >> 7, p = i & 127;
        ob[(size_t)o*HW + p] = sOut[i];
    }
}

// ---------------------------------------------------------------------------
extern "C" void kernel_launch(void* const* d_in, const int* in_sizes, int n_in,
                              void* d_out, int out_size)
{
    const float* x      = (const float*)d_in[0];
    const float* w_off  = (const float*)d_in[1];
    const float* b_off  = (const float*)d_in[2];
    const float* weight = (const float*)d_in[3];
    const float* bias   = (const float*)d_in[4];
    float* out = (float*)d_out;

    static bool attr_done = false;
    if (!attr_done) {
        cudaFuncSetAttribute(dc_offsets, cudaFuncAttributeMaxDynamicSharedMemorySize,
                             B_SMEM_FLOATS * (int)sizeof(float));
        cudaFuncSetAttribute(dc_main, cudaFuncAttributeMaxDynamicSharedMemorySize,
                             C_SMEM_FLOATS * (int)sizeof(float));
        attr_done = true;
    }

    dc_transpose<<<Bdim * (HW/64), 256>>>(x);
    dc_wtrans   <<<(9*64*64 + 255)/256, 256>>>(weight);
    dc_offsets  <<<PTOT/32, 256, B_SMEM_FLOATS * sizeof(float)>>>(w_off, b_off);
    dc_main     <<<Bdim * 72, 256, C_SMEM_FLOATS * sizeof(float)>>>(bias, out);
}

// round 3
// speedup vs baseline: 1.7981x; 1.6125x over previous
#include <cuda_runtime.h>
#include <math.h>

#define CIN   64
#define COUT  64
#define Hdim  96
#define Wdim  96
#define Bdim  8
#define HW    (Hdim*Wdim)     /* 9216  */
#define PTOT  (Bdim*HW)       /* 73728 */

typedef unsigned long long u64;

// Scratch (no cudaMalloc allowed). g_xt padded +64 floats for column-overhang reads.
__device__ float g_xt [PTOT*CIN + 64];   // NHWC x: [(b*HW+h*96+w)*64 + c]
__device__ float g_pos[PTOT*9*3];        // per (pixel,k): ys, xs, mask
__device__ float g_wt2[9*64*80];         // weights: [k][c][ogrp*20 + i], o=ogrp*16+i (pad 4/grp)
__device__ float g_wo [9*27*68];         // offset weights: [kk][m][c] (c-stride 68)

// ---------------- helpers --------------------------------------------------
__device__ __forceinline__ u64 pack2(float lo, float hi) {
    u64 r; asm("mov.b64 %0, {%1,%2};" : "=l"(r) : "f"(lo), "f"(hi)); return r;
}
__device__ __forceinline__ void unpack2(u64 v, float& lo, float& hi) {
    asm("mov.b64 {%0,%1}, %2;" : "=f"(lo), "=f"(hi) : "l"(v));
}
__device__ __forceinline__ u64 ffma2(u64 a, u64 b, u64 c) {
    u64 d; asm("fma.rn.f32x2 %0, %1, %2, %3;" : "=l"(d) : "l"(a), "l"(b), "l"(c));
    return d;
}
__device__ __forceinline__ void cp_async16(unsigned saddr, const void* g) {
    asm volatile("cp.async.cg.shared.global [%0], [%1], 16;" :: "r"(saddr), "l"(g));
}
__device__ __forceinline__ void cp_commit() { asm volatile("cp.async.commit_group;"); }
__device__ __forceinline__ void cp_wait0()  { asm volatile("cp.async.wait_group 0;"); }

// ---------------------------------------------------------------------------
// Kernel A: NCHW -> NHWC transpose of x
// ---------------------------------------------------------------------------
__global__ __launch_bounds__(256) void dc_transpose(const float* __restrict__ x)
{
    __shared__ float tile[64*65];
    int b  = blockIdx.x / 144;
    int s0 = (blockIdx.x % 144) * 64;
    const float* xb = x + (size_t)b * CIN * HW;
    for (int i = threadIdx.x; i < 64*64; i += 256) {
        int c = i >> 6, s = i & 63;
        tile[c*65 + s] = xb[(size_t)c*HW + s0 + s];
    }
    __syncthreads();
    float* xtb = g_xt + ((size_t)b*HW + s0) * 64;
    for (int i = threadIdx.x; i < 64*64; i += 256) {
        int s = i >> 6, c = i & 63;
        xtb[s*64 + c] = tile[c*65 + s];
    }
    if (blockIdx.x == 0 && threadIdx.x < 64)
        g_xt[(size_t)PTOT*CIN + threadIdx.x] = 0.f;   // zero the overhang pad
}

// ---------------------------------------------------------------------------
// Kernel A2: weight [o][c][k] -> g_wt2[k][c][ogrp*20+i] ; offset w -> g_wo
// ---------------------------------------------------------------------------
__global__ __launch_bounds__(256) void dc_wtrans(const float* __restrict__ w,
                                                 const float* __restrict__ wo)
{
    int i = blockIdx.x * 256 + threadIdx.x;
    if (i < 9*64*64) {                       // main weights
        int o = i / 576, r = i % 576, c = r / 9, k = r % 9;
        int g = o >> 4, oi = o & 15;
        g_wt2[(k*64 + c)*80 + g*20 + oi] = w[i];
    }
    if (i < 27*64*9) {                       // offset weights [m][c][kk]
        int m = i / 576, rr = i % 576, c = rr / 9, kk = rr % 9;
        g_wo[(kk*27 + m)*68 + c] = wo[i];
    }
}

// ---------------------------------------------------------------------------
// Kernel B: offset conv (27 out-ch, 3x3) -> (ys, xs, mask)
// ---------------------------------------------------------------------------
#define B_SP_OFF   0
#define B_SP_SIZE  (3*34*68)
#define B_SW_OFF   (B_SP_OFF + B_SP_SIZE)
#define B_SW_SIZE  (9*27*68)
#define B_OM_OFF   (B_SW_OFF + B_SW_SIZE)
#define B_OM_SIZE  (32*28)
#define B_SMEM_FLOATS (B_OM_OFF + B_OM_SIZE)

__global__ __launch_bounds__(256) void dc_offsets(const float* __restrict__ b_off)
{
    extern __shared__ float sm[];
    float* sP  = sm + B_SP_OFF;
    float* sWo = sm + B_SW_OFF;
    float* sOm = sm + B_OM_OFF;
    unsigned swBase = (unsigned)__cvta_generic_to_shared(sWo);

    int tid  = threadIdx.x;
    int tile = blockIdx.x * 32;
    int b    = tile / HW;
    int rem  = tile % HW;
    int h    = rem / Wdim;
    int w0   = rem % Wdim;

    // weights: straight cp.async copy (pre-relaid in g_wo)
    for (int i = tid; i < (9*27*68)/4; i += 256)
        cp_async16(swBase + (unsigned)i*16u, g_wo + i*4);
    cp_commit();

    // input patch (NHWC), 3 rows x 34 cols
    const float* xtb = g_xt + (size_t)b * HW * 64;
    for (int r = 0; r < 3; r++) {
        int hh = h - 1 + r;
        bool rv = (hh >= 0) & (hh < Hdim);
        for (int i = tid; i < 34*64; i += 256) {
            int col = i >> 6, c = i & 63;
            int ww = w0 - 1 + col;
            float v = 0.f;
            if (rv && ww >= 0 && ww < Wdim)
                v = xtb[((size_t)hh*Wdim + ww)*64 + c];
            sP[(r*34 + col)*68 + c] = v;
        }
    }
    cp_wait0();
    __syncthreads();

    int px = tid >> 3;
    int j  = tid & 7;
    int m3 = (j < 3) ? (j + 24) : j;     // dummy row for j>=3 (discarded)
    u64 acc0 = 0, acc1 = 0, acc2 = 0, acc3 = 0;

    #pragma unroll
    for (int kk = 0; kk < 9; kk++) {
        int ky = kk / 3, kx = kk % 3;
        const float* xr  = sP  + (ky*34 + px + kx)*68;
        const float* wr0 = sWo + (kk*27 + j     )*68;
        const float* wr1 = sWo + (kk*27 + j + 8 )*68;
        const float* wr2 = sWo + (kk*27 + j + 16)*68;
        const float* wr3 = sWo + (kk*27 + m3    )*68;
        #pragma unroll
        for (int c4 = 0; c4 < 16; c4++) {
            ulonglong2 xv = *(const ulonglong2*)(xr + c4*4);
            ulonglong2 wv;
            wv = *(const ulonglong2*)(wr0 + c4*4);
            acc0 = ffma2(xv.x, wv.x, acc0); acc0 = ffma2(xv.y, wv.y, acc0);
            wv = *(const ulonglong2*)(wr1 + c4*4);
            acc1 = ffma2(xv.x, wv.x, acc1); acc1 = ffma2(xv.y, wv.y, acc1);
            wv = *(const ulonglong2*)(wr2 + c4*4);
            acc2 = ffma2(xv.x, wv.x, acc2); acc2 = ffma2(xv.y, wv.y, acc2);
            wv = *(const ulonglong2*)(wr3 + c4*4);
            acc3 = ffma2(xv.x, wv.x, acc3); acc3 = ffma2(xv.y, wv.y, acc3);
        }
    }
    float lo, hi, s0, s1, s2, s3;
    unpack2(acc0, lo, hi); s0 = lo + hi;
    unpack2(acc1, lo, hi); s1 = lo + hi;
    unpack2(acc2, lo, hi); s2 = lo + hi;
    unpack2(acc3, lo, hi); s3 = lo + hi;
    __syncthreads();
    sOm[px*28 + j     ] = s0 + b_off[j];
    sOm[px*28 + j + 8 ] = s1 + b_off[j + 8];
    sOm[px*28 + j + 16] = s2 + b_off[j + 16];
    if (j < 3) sOm[px*28 + j + 24] = s3 + b_off[j + 24];
    __syncthreads();

    for (int idx = tid; idx < 32*9; idx += 256) {
        int p2 = idx / 9, k = idx % 9;
        float dy = sOm[p2*28 + 2*k];
        float dx = sOm[p2*28 + 2*k + 1];
        float mv = sOm[p2*28 + 18 + k];
        float mask = 1.0f / (1.0f + __expf(-mv));
        int ky = k / 3, kx = k % 3;
        float ys = (float)(h - 1 + ky) + dy;
        float xs = (float)(w0 + p2 - 1 + kx) + dx;
        float* gp = g_pos + (size_t)(tile + p2)*27 + k*3;
        gp[0] = ys; gp[1] = xs; gp[2] = mask;
    }
}

// ---------------------------------------------------------------------------
// Kernel C: fused sample + GEMM.  Block = 128 px, 256 threads, 1 block/SM.
// smem: sW2 2x5120, sS 2x(128*68), sCoef 1152 float4, sBase 1152 int2.
// ---------------------------------------------------------------------------
#define C_SW0    0
#define C_SW1    5120
#define C_SS0    10240
#define C_SS1    (10240 + 128*68)
#define C_COEF   (10240 + 2*128*68)            /* 27648 */
#define C_BASE   (C_COEF + 1152*4)             /* 32256 (ints) */
#define C_SMEM_FLOATS (C_BASE + 1152*2)        /* 34560 = 138.2 KB */

__global__ __launch_bounds__(256, 1) void dc_main(const float* __restrict__ bias,
                                                  float* __restrict__ out)
{
    extern __shared__ float sm[];
    float4* sCoef = (float4*)(sm + C_COEF);
    int2*   sBase = (int2*)  (sm + C_BASE);
    unsigned smW0 = (unsigned)__cvta_generic_to_shared(sm + C_SW0);
    unsigned smW1 = (unsigned)__cvta_generic_to_shared(sm + C_SW1);

    int tid = threadIdx.x;
    int lane = tid & 31;
    int b      = blockIdx.x / 72;
    int pxBase = (blockIdx.x % 72) * 128;
    int gpixBase = b * HW + pxBase;
    const float* xtb = g_xt + (size_t)b * HW * 64;

    // ---- meta precompute: per (px,k) coefs + clamped row bases
    for (int i = tid; i < 1152; i += 256) {
        int px = i / 9, k = i % 9;
        const float* gp = g_pos + (size_t)(gpixBase + px)*27 + k*3;
        float ys = gp[0], xs = gp[1], mk = gp[2];
        float y0f = floorf(ys), x0f = floorf(xs);
        float ty = ys - y0f, tx = xs - x0f;
        int iy0 = (int)y0f, ix0 = (int)x0f;
        float wy0 = (iy0 >= 0 && iy0 <= Hdim-1) ? (1.f - ty) : 0.f;
        float wy1 = (iy0+1 >= 0 && iy0+1 <= Hdim-1) ? ty : 0.f;
        float wx0 = (ix0 >= 0 && ix0 <= Wdim-1) ? (1.f - tx) : 0.f;
        float wx1 = (ix0+1 >= 0 && ix0+1 <= Wdim-1) ? tx : 0.f;
        int bx = min(max(ix0, 0), Wdim-1);
        // coef for mem-col0 (x=bx) and mem-col1 (x=bx+1), handling the shift at ix0=-1
        float cx0 = (ix0 == bx) ? wx0 : ((ix0 + 1 == bx) ? wx1 : 0.f);
        float cx1 = (ix0 == bx) ? wx1 : 0.f;
        int cy0 = min(max(iy0,   0), Hdim-1);
        int cy1 = min(max(iy0+1, 0), Hdim-1);
        float4 cf;
        cf.x = wy0*cx0*mk;  cf.y = wy0*cx1*mk;   // row0: col0, col1
        cf.z = wy1*cx0*mk;  cf.w = wy1*cx1*mk;   // row1
        sCoef[k*128 + px] = cf;
        sBase[k*128 + px] = make_int2((cy0*Wdim + bx)*64, (cy1*Wdim + bx)*64);
    }
    __syncthreads();

    // GEMM mapping
    int pp = tid >> 2, j = tid & 3;
    int pxA = pp, pxB = pp + 64;
    // gather mapping
    int warpPx0 = (tid >> 5) * 16;
    int col = lane >> 4;

    u64 accA[8], accB[8];
    #pragma unroll
    for (int q = 0; q < 8; q++) {
        float b0 = __ldg(&bias[j*16 + 2*q]);
        float b1 = __ldg(&bias[j*16 + 2*q + 1]);
        accA[q] = pack2(b0, b1);
        accB[q] = pack2(b0, b1);
    }

    // ---- prologue: weights k=0 + gather k=0 into sS0
    for (int i = tid; i < 1280; i += 256)
        cp_async16(smW0 + (unsigned)i*16u, g_wt2 + i*4);
    cp_commit();
    {
        float* dst = sm + C_SS0;
        for (int ch = 0; ch < 4; ch++) {
            int px0 = warpPx0 + ch*4;
            #pragma unroll
            for (int p = 0; p < 4; p++) {
                int mi = 0*128 + px0 + p;
                int2 bs = sBase[mi];
                float4 cf = sCoef[mi];
                float4 q0 = *(const float4*)(xtb + bs.x + lane*4);
                float4 q1 = *(const float4*)(xtb + bs.y + lane*4);
                float c0 = col ? cf.y : cf.x;
                float c1 = col ? cf.w : cf.z;
                float4 t;
                t.x = q0.x*c0 + q1.x*c1;  t.y = q0.y*c0 + q1.y*c1;
                t.z = q0.z*c0 + q1.z*c1;  t.w = q0.w*c0 + q1.w*c1;
                t.x += __shfl_xor_sync(0xffffffffu, t.x, 16);
                t.y += __shfl_xor_sync(0xffffffffu, t.y, 16);
                t.z += __shfl_xor_sync(0xffffffffu, t.z, 16);
                t.w += __shfl_xor_sync(0xffffffffu, t.w, 16);
                if (lane < 16) *(float4*)(dst + (px0+p)*68 + lane*4) = t;
            }
        }
    }
    cp_wait0();
    __syncthreads();

    // ---- main loop
    for (int k = 0; k < 9; k++) {
        int cur = k & 1, nxt = cur ^ 1;
        if (k < 8) {   // stream weights k+1
            unsigned dstW = nxt ? smW1 : smW0;
            const float* srcW = g_wt2 + (k+1)*5120;
            for (int i = tid; i < 1280; i += 256)
                cp_async16(dstW + (unsigned)i*16u, srcW + i*4);
            cp_commit();
        }
        const float* ss = sm + (cur ? C_SS1 : C_SS0);
        const float* wk = sm + (cur ? C_SW1 : C_SW0);
        float* gdst     = sm + (nxt ? C_SS1 : C_SS0);

        #pragma unroll
        for (int ch = 0; ch < 4; ch++) {
            // -- gather(k+1) chunk: issue LDGs early
            float4 gq0[4], gq1[4]; float4 gcf[4];
            int px0 = warpPx0 + ch*4;
            if (k < 8) {
                #pragma unroll
                for (int p = 0; p < 4; p++) {
                    int mi = (k+1)*128 + px0 + p;
                    int2 bs = sBase[mi];
                    gcf[p] = sCoef[mi];
                    gq0[p] = *(const float4*)(xtb + bs.x + lane*4);
                    gq1[p] = *(const float4*)(xtb + bs.y + lane*4);
                }
            }
            // -- GEMM over 4 channels-of-4 (c4 = ch*4 .. ch*4+3)
            #pragma unroll
            for (int t4 = 0; t4 < 4; t4++) {
                int c4 = ch*4 + t4;
                float4 xa = *(const float4*)(ss + pxA*68 + c4*4);
                float4 xb = *(const float4*)(ss + pxB*68 + c4*4);
                #pragma unroll
                for (int cc = 0; cc < 4; cc++) {
                    float xac = (cc==0)?xa.x:(cc==1)?xa.y:(cc==2)?xa.z:xa.w;
                    float xbc = (cc==0)?xb.x:(cc==1)?xb.y:(cc==2)?xb.z:xb.w;
                    u64 xaP = pack2(xac, xac);
                    u64 xbP = pack2(xbc, xbc);
                    const float* wr = wk + (c4*4 + cc)*80 + j*20;
                    ulonglong2 wv0 = *(const ulonglong2*)(wr);
                    ulonglong2 wv1 = *(const ulonglong2*)(wr + 4);
                    ulonglong2 wv2 = *(const ulonglong2*)(wr + 8);
                    ulonglong2 wv3 = *(const ulonglong2*)(wr + 12);
                    accA[0] = ffma2(xaP, wv0.x, accA[0]);
                    accA[1] = ffma2(xaP, wv0.y, accA[1]);
                    accA[2] = ffma2(xaP, wv1.x, accA[2]);
                    accA[3] = ffma2(xaP, wv1.y, accA[3]);
                    accA[4] = ffma2(xaP, wv2.x, accA[4]);
                    accA[5] = ffma2(xaP, wv2.y, accA[5]);
                    accA[6] = ffma2(xaP, wv3.x, accA[6]);
                    accA[7] = ffma2(xaP, wv3.y, accA[7]);
                    accB[0] = ffma2(xbP, wv0.x, accB[0]);
                    accB[1] = ffma2(xbP, wv0.y, accB[1]);
                    accB[2] = ffma2(xbP, wv1.x, accB[2]);
                    accB[3] = ffma2(xbP, wv1.y, accB[3]);
                    accB[4] = ffma2(xbP, wv2.x, accB[4]);
                    accB[5] = ffma2(xbP, wv2.y, accB[5]);
                    accB[6] = ffma2(xbP, wv3.x, accB[6]);
                    accB[7] = ffma2(xbP, wv3.y, accB[7]);
                }
            }
            // -- gather(k+1) chunk: combine + STS
            if (k < 8) {
                #pragma unroll
                for (int p = 0; p < 4; p++) {
                    float c0 = col ? gcf[p].y : gcf[p].x;
                    float c1 = col ? gcf[p].w : gcf[p].z;
                    float4 t;
                    t.x = gq0[p].x*c0 + gq1[p].x*c1;
                    t.y = gq0[p].y*c0 + gq1[p].y*c1;
                    t.z = gq0[p].z*c0 + gq1[p].z*c1;
                    t.w = gq0[p].w*c0 + gq1[p].w*c1;
                    t.x += __shfl_xor_sync(0xffffffffu, t.x, 16);
                    t.y += __shfl_xor_sync(0xffffffffu, t.y, 16);
                    t.z += __shfl_xor_sync(0xffffffffu, t.z, 16);
                    t.w += __shfl_xor_sync(0xffffffffu, t.w, 16);
                    if (lane < 16) *(float4*)(gdst + (px0+p)*68 + lane*4) = t;
                }
            }
        }
        cp_wait0();
        __syncthreads();
    }

    // ---- epilogue: stage [o][px], coalesced NCHW store
    float* sOut = sm + C_SS0;   // 8192 floats, safe (all GEMM reads done)
    #pragma unroll
    for (int q = 0; q < 8; q++) {
        int o = j*16 + 2*q;
        float lo, hi;
        unpack2(accA[q], lo, hi);
        sOut[o*128 + pxA] = lo;  sOut[(o+1)*128 + pxA] = hi;
        unpack2(accB[q], lo, hi);
        sOut[o*128 + pxB] = lo;  sOut[(o+1)*128 + pxB] = hi;
    }
    __syncthreads();
    float* ob = out + (size_t)b * COUT * HW + pxBase;
    for (int i = tid; i < 64*128; i += 256) {
        int o = i >> 7, p = i & 127;
        ob[(size_t)o*HW + p] = sOut[i];
    }
}

// ---------------------------------------------------------------------------
extern "C" void kernel_launch(void* const* d_in, const int* in_sizes, int n_in,
                              void* d_out, int out_size)
{
    const float* x      = (const float*)d_in[0];
    const float* w_off  = (const float*)d_in[1];
    const float* b_off  = (const float*)d_in[2];
    const float* weight = (const float*)d_in[3];
    const float* bias   = (const float*)d_in[4];
    float* out = (float*)d_out;

    static bool attr_done = false;
    if (!attr_done) {
        cudaFuncSetAttribute(dc_offsets, cudaFuncAttributeMaxDynamicSharedMemorySize,
                             B_SMEM_FLOATS * (int)sizeof(float));
        cudaFuncSetAttribute(dc_main, cudaFuncAttributeMaxDynamicSharedMemorySize,
                             C_SMEM_FLOATS * (int)sizeof(float));
        attr_done = true;
    }

    dc_transpose<<<Bdim * (HW/64), 256>>>(x);
    dc_wtrans   <<<(9*64*64 + 255)/256, 256>>>(weight, w_off);
    dc_offsets  <<<PTOT/32, 256, B_SMEM_FLOATS * sizeof(float)>>>(b_off);
    dc_main     <<<Bdim * 72, 256, C_SMEM_FLOATS * sizeof(float)>>>(bias, out);
}

// round 4
// speedup vs baseline: 2.1048x; 1.1705x over previous
#include <cuda_runtime.h>
#include <math.h>

#define CIN   64
#define COUT  64
#define Hdim  96
#define Wdim  96
#define Bdim  8
#define HW    (Hdim*Wdim)     /* 9216  */
#define PTOT  (Bdim*HW)       /* 73728 */

typedef unsigned long long u64;

// Scratch (no cudaMalloc allowed). g_xt padded +64 floats for column-overhang reads.
__device__ float g_xt [PTOT*CIN + 64];   // NHWC x: [(b*HW+h*96+w)*64 + c]
__device__ float g_pos[PTOT*9*3];        // per (pixel,k): ys, xs, mask
__device__ float g_wt3[9*64*96];         // weights: [k][c][ogrp*12 + i], o=ogrp*8+i (pad 4/grp)
__device__ float g_wo [9*27*68];         // offset weights: [kk][m][c] (c-stride 68)

// ---------------- helpers --------------------------------------------------
__device__ __forceinline__ u64 pack2(float lo, float hi) {
    u64 r; asm("mov.b64 %0, {%1,%2};" : "=l"(r) : "f"(lo), "f"(hi)); return r;
}
__device__ __forceinline__ void unpack2(u64 v, float& lo, float& hi) {
    asm("mov.b64 {%0,%1}, %2;" : "=f"(lo), "=f"(hi) : "l"(v));
}
__device__ __forceinline__ u64 ffma2(u64 a, u64 b, u64 c) {
    u64 d; asm("fma.rn.f32x2 %0, %1, %2, %3;" : "=l"(d) : "l"(a), "l"(b), "l"(c));
    return d;
}
__device__ __forceinline__ void cp_async16(unsigned saddr, const void* g) {
    asm volatile("cp.async.cg.shared.global [%0], [%1], 16;" :: "r"(saddr), "l"(g));
}
__device__ __forceinline__ void cp_commit() { asm volatile("cp.async.commit_group;"); }
__device__ __forceinline__ void cp_wait0()  { asm volatile("cp.async.wait_group 0;"); }

// ---------------------------------------------------------------------------
// Kernel A: NCHW -> NHWC transpose of x
// ---------------------------------------------------------------------------
__global__ __launch_bounds__(256) void dc_transpose(const float* __restrict__ x)
{
    __shared__ float tile[64*65];
    int b  = blockIdx.x / 144;
    int s0 = (blockIdx.x % 144) * 64;
    const float* xb = x + (size_t)b * CIN * HW;
    for (int i = threadIdx.x; i < 64*64; i += 256) {
        int c = i >> 6, s = i & 63;
        tile[c*65 + s] = xb[(size_t)c*HW + s0 + s];
    }
    __syncthreads();
    float* xtb = g_xt + ((size_t)b*HW + s0) * 64;
    for (int i = threadIdx.x; i < 64*64; i += 256) {
        int s = i >> 6, c = i & 63;
        xtb[s*64 + c] = tile[c*65 + s];
    }
    if (blockIdx.x == 0 && threadIdx.x < 64)
        g_xt[(size_t)PTOT*CIN + threadIdx.x] = 0.f;
}

// ---------------------------------------------------------------------------
// Kernel A2: weight [o][c][k] -> g_wt3[k][c][ogrp*12+i] ; offset w -> g_wo
// ---------------------------------------------------------------------------
__global__ __launch_bounds__(256) void dc_wtrans(const float* __restrict__ w,
                                                 const float* __restrict__ wo)
{
    int i = blockIdx.x * 256 + threadIdx.x;
    if (i < 9*64*64) {                       // main weights
        int o = i / 576, r = i % 576, c = r / 9, k = r % 9;
        int g = o >> 3, oi = o & 7;
        g_wt3[(k*64 + c)*96 + g*12 + oi] = w[i];
    }
    if (i < 27*64*9) {                       // offset weights [m][c][kk]
        int m = i / 576, rr = i % 576, c = rr / 9, kk = rr % 9;
        g_wo[(kk*27 + m)*68 + c] = wo[i];
    }
}

// ---------------------------------------------------------------------------
// Kernel B: offset conv (27 out-ch, 3x3) -> (ys, xs, mask)
// Block = one full image row (96 px), 384 threads.
// Thread = 2 px (pp, pp+48) x 4 m-channels {j, j+8, j+16, j+24(dummy j>=3)}.
// ---------------------------------------------------------------------------
#define B_SP_SIZE  (3*98*68)                 /* 19992 */
#define B_SW_OFF   B_SP_SIZE
#define B_SW_SIZE  (9*27*68)                 /* 16524 */
#define B_OM_OFF   (B_SW_OFF + B_SW_SIZE)
#define B_OM_SIZE  (96*28)
#define B_SMEM_FLOATS (B_OM_OFF + B_OM_SIZE) /* 39204 floats = 156.8 KB */

__global__ __launch_bounds__(384, 1) void dc_offsets(const float* __restrict__ b_off)
{
    extern __shared__ float sm[];
    float* sP  = sm;
    float* sWo = sm + B_SW_OFF;
    float* sOm = sm + B_OM_OFF;
    unsigned swBase = (unsigned)__cvta_generic_to_shared(sWo);

    int tid = threadIdx.x;
    int b   = blockIdx.x / Hdim;
    int h   = blockIdx.x % Hdim;
    int gpixBase = b * HW + h * Wdim;

    // weights: straight cp.async copy (pre-relaid in g_wo)
    for (int i = tid; i < (9*27*68)/4; i += 384)
        cp_async16(swBase + (unsigned)i*16u, g_wo + i*4);
    cp_commit();

    // input patch: 3 rows x 98 cols (cols -1..96), zero outside
    const float* xtb = g_xt + (size_t)b * HW * 64;
    for (int r = 0; r < 3; r++) {
        int hh = h - 1 + r;
        bool rv = (hh >= 0) & (hh < Hdim);
        for (int i = tid; i < 98*64; i += 384) {
            int col = i >> 6, c = i & 63;
            int ww = col - 1;
            float v = 0.f;
            if (rv && ww >= 0 && ww < Wdim)
                v = xtb[((size_t)hh*Wdim + ww)*64 + c];
            sP[(r*98 + col)*68 + c] = v;
        }
    }
    cp_wait0();
    __syncthreads();

    int pp = tid >> 3;              // 0..47
    int j  = tid & 7;
    int m3 = (j < 3) ? (j + 24) : j;
    int pxA = pp, pxB = pp + 48;

    u64 a0=0, a1=0, a2=0, a3=0, c0=0, c1=0, c2=0, c3=0;

    #pragma unroll
    for (int kk = 0; kk < 9; kk++) {
        int ky = kk / 3, kx = kk % 3;
        const float* xrA = sP + (ky*98 + pxA + kx)*68;
        const float* xrB = sP + (ky*98 + pxB + kx)*68;
        const float* wr0 = sWo + (kk*27 + j     )*68;
        const float* wr1 = sWo + (kk*27 + j + 8 )*68;
        const float* wr2 = sWo + (kk*27 + j + 16)*68;
        const float* wr3 = sWo + (kk*27 + m3    )*68;
        #pragma unroll
        for (int c4 = 0; c4 < 16; c4++) {
            ulonglong2 xa = *(const ulonglong2*)(xrA + c4*4);
            ulonglong2 xb = *(const ulonglong2*)(xrB + c4*4);
            ulonglong2 wv;
            wv = *(const ulonglong2*)(wr0 + c4*4);
            a0 = ffma2(xa.x, wv.x, a0); a0 = ffma2(xa.y, wv.y, a0);
            c0 = ffma2(xb.x, wv.x, c0); c0 = ffma2(xb.y, wv.y, c0);
            wv = *(const ulonglong2*)(wr1 + c4*4);
            a1 = ffma2(xa.x, wv.x, a1); a1 = ffma2(xa.y, wv.y, a1);
            c1 = ffma2(xb.x, wv.x, c1); c1 = ffma2(xb.y, wv.y, c1);
            wv = *(const ulonglong2*)(wr2 + c4*4);
            a2 = ffma2(xa.x, wv.x, a2); a2 = ffma2(xa.y, wv.y, a2);
            c2 = ffma2(xb.x, wv.x, c2); c2 = ffma2(xb.y, wv.y, c2);
            wv = *(const ulonglong2*)(wr3 + c4*4);
            a3 = ffma2(xa.x, wv.x, a3); a3 = ffma2(xa.y, wv.y, a3);
            c3 = ffma2(xb.x, wv.x, c3); c3 = ffma2(xb.y, wv.y, c3);
        }
    }
    float lo, hi;
    float bj0 = b_off[j], bj1 = b_off[j+8], bj2 = b_off[j+16];
    float bj3 = (j < 3) ? b_off[j+24] : 0.f;
    __syncthreads();
    unpack2(a0, lo, hi); sOm[pxA*28 + j     ] = lo + hi + bj0;
    unpack2(a1, lo, hi); sOm[pxA*28 + j + 8 ] = lo + hi + bj1;
    unpack2(a2, lo, hi); sOm[pxA*28 + j + 16] = lo + hi + bj2;
    unpack2(c0, lo, hi); sOm[pxB*28 + j     ] = lo + hi + bj0;
    unpack2(c1, lo, hi); sOm[pxB*28 + j + 8 ] = lo + hi + bj1;
    unpack2(c2, lo, hi); sOm[pxB*28 + j + 16] = lo + hi + bj2;
    if (j < 3) {
        unpack2(a3, lo, hi); sOm[pxA*28 + j + 24] = lo + hi + bj3;
        unpack2(c3, lo, hi); sOm[pxB*28 + j + 24] = lo + hi + bj3;
    }
    __syncthreads();

    for (int idx = tid; idx < 96*9; idx += 384) {
        int p2 = idx / 9, k = idx % 9;
        float dy = sOm[p2*28 + 2*k];
        float dx = sOm[p2*28 + 2*k + 1];
        float mv = sOm[p2*28 + 18 + k];
        float mask = 1.0f / (1.0f + __expf(-mv));
        int ky = k / 3, kx = k % 3;
        float ys = (float)(h - 1 + ky) + dy;
        float xs = (float)(p2 - 1 + kx) + dx;
        float* gp = g_pos + (size_t)(gpixBase + p2)*27 + k*3;
        gp[0] = ys; gp[1] = xs; gp[2] = mask;
    }
}

// ---------------------------------------------------------------------------
// Kernel C: fused sample + GEMM.  Block = 128 px, 512 threads (16 warps).
// Thread = (pp = tid>>3: px pp & pp+64) x (j = tid&7: 8 outputs o=j*8..j*8+7).
// smem: sW 2x6144 (stride 96/c-row), sS 2x(128*68), sCoef, sBase.
// ---------------------------------------------------------------------------
#define C_SW0    0
#define C_SW1    6144
#define C_SS0    12288
#define C_SS1    (12288 + 128*68)
#define C_COEF   (12288 + 2*128*68)            /* 29696 */
#define C_BASE   (C_COEF + 1152*4)             /* 34304 */
#define C_SMEM_FLOATS (C_BASE + 1152*2)        /* 36608 = 146.4 KB */

__global__ __launch_bounds__(512, 1) void dc_main(const float* __restrict__ bias,
                                                  float* __restrict__ out)
{
    extern __shared__ float sm[];
    float4* sCoef = (float4*)(sm + C_COEF);
    int2*   sBase = (int2*)  (sm + C_BASE);
    unsigned smW0 = (unsigned)__cvta_generic_to_shared(sm + C_SW0);
    unsigned smW1 = (unsigned)__cvta_generic_to_shared(sm + C_SW1);

    int tid = threadIdx.x;
    int lane = tid & 31;
    int b      = blockIdx.x / 72;
    int pxBase = (blockIdx.x % 72) * 128;
    int gpixBase = b * HW + pxBase;
    const float* xtb = g_xt + (size_t)b * HW * 64;

    // ---- meta precompute: per (px,k) coefs + clamped row bases
    for (int i = tid; i < 1152; i += 512) {
        int px = i / 9, k = i % 9;
        const float* gp = g_pos + (size_t)(gpixBase + px)*27 + k*3;
        float ys = gp[0], xs = gp[1], mk = gp[2];
        float y0f = floorf(ys), x0f = floorf(xs);
        float ty = ys - y0f, tx = xs - x0f;
        int iy0 = (int)y0f, ix0 = (int)x0f;
        float wy0 = (iy0 >= 0 && iy0 <= Hdim-1) ? (1.f - ty) : 0.f;
        float wy1 = (iy0+1 >= 0 && iy0+1 <= Hdim-1) ? ty : 0.f;
        float wx0 = (ix0 >= 0 && ix0 <= Wdim-1) ? (1.f - tx) : 0.f;
        float wx1 = (ix0+1 >= 0 && ix0+1 <= Wdim-1) ? tx : 0.f;
        int bx = min(max(ix0, 0), Wdim-1);
        float cx0 = (ix0 == bx) ? wx0 : ((ix0 + 1 == bx) ? wx1 : 0.f);
        float cx1 = (ix0 == bx) ? wx1 : 0.f;
        int cy0 = min(max(iy0,   0), Hdim-1);
        int cy1 = min(max(iy0+1, 0), Hdim-1);
        float4 cf;
        cf.x = wy0*cx0*mk;  cf.y = wy0*cx1*mk;
        cf.z = wy1*cx0*mk;  cf.w = wy1*cx1*mk;
        sCoef[k*128 + px] = cf;
        sBase[k*128 + px] = make_int2((cy0*Wdim + bx)*64, (cy1*Wdim + bx)*64);
    }
    __syncthreads();

    // GEMM mapping
    int pp = tid >> 3, j = tid & 7;
    int pxA = pp, pxB = pp + 64;
    // gather mapping: warp handles 8 px
    int warpPx0 = (tid >> 5) * 8;
    int col = lane >> 4;

    u64 accA[4], accB[4];
    #pragma unroll
    for (int q = 0; q < 4; q++) {
        float b0 = __ldg(&bias[j*8 + 2*q]);
        float b1 = __ldg(&bias[j*8 + 2*q + 1]);
        accA[q] = pack2(b0, b1);
        accB[q] = pack2(b0, b1);
    }

    // ---- prologue: weights k=0 + gather k=0 into sS0
    for (int i = tid; i < 1536; i += 512)
        cp_async16(smW0 + (unsigned)i*16u, g_wt3 + i*4);
    cp_commit();
    {
        float* dst = sm + C_SS0;
        #pragma unroll
        for (int ch = 0; ch < 4; ch++) {
            int px0 = warpPx0 + ch*2;
            #pragma unroll
            for (int p = 0; p < 2; p++) {
                int mi = 0*128 + px0 + p;
                int2 bs = sBase[mi];
                float4 cf = sCoef[mi];
                float4 q0 = *(const float4*)(xtb + bs.x + lane*4);
                float4 q1 = *(const float4*)(xtb + bs.y + lane*4);
                float cc0 = col ? cf.y : cf.x;
                float cc1 = col ? cf.w : cf.z;
                float4 t;
                t.x = q0.x*cc0 + q1.x*cc1;  t.y = q0.y*cc0 + q1.y*cc1;
                t.z = q0.z*cc0 + q1.z*cc1;  t.w = q0.w*cc0 + q1.w*cc1;
                t.x += __shfl_xor_sync(0xffffffffu, t.x, 16);
                t.y += __shfl_xor_sync(0xffffffffu, t.y, 16);
                t.z += __shfl_xor_sync(0xffffffffu, t.z, 16);
                t.w += __shfl_xor_sync(0xffffffffu, t.w, 16);
                if (lane < 16) *(float4*)(dst + (px0+p)*68 + lane*4) = t;
            }
        }
    }
    cp_wait0();
    __syncthreads();

    // ---- main loop
    for (int k = 0; k < 9; k++) {
        int cur = k & 1, nxt = cur ^ 1;
        if (k < 8) {   // stream weights k+1
            unsigned dstW = nxt ? smW1 : smW0;
            const float* srcW = g_wt3 + (k+1)*6144;
            for (int i = tid; i < 1536; i += 512)
                cp_async16(dstW + (unsigned)i*16u, srcW + i*4);
            cp_commit();
        }
        const float* ss = sm + (cur ? C_SS1 : C_SS0);
        const float* wk = sm + (cur ? C_SW1 : C_SW0);
        float* gdst     = sm + (nxt ? C_SS1 : C_SS0);

        #pragma unroll
        for (int ch = 0; ch < 4; ch++) {
            // -- gather(k+1) chunk: issue LDGs early
            float4 gq0[2], gq1[2]; float4 gcf[2];
            int px0 = warpPx0 + ch*2;
            if (k < 8) {
                #pragma unroll
                for (int p = 0; p < 2; p++) {
                    int mi = (k+1)*128 + px0 + p;
                    int2 bs = sBase[mi];
                    gcf[p] = sCoef[mi];
                    gq0[p] = *(const float4*)(xtb + bs.x + lane*4);
                    gq1[p] = *(const float4*)(xtb + bs.y + lane*4);
                }
            }
            // -- GEMM over channels c4 = ch*4 .. ch*4+3
            #pragma unroll
            for (int t4 = 0; t4 < 4; t4++) {
                int c4 = ch*4 + t4;
                float4 xa = *(const float4*)(ss + pxA*68 + c4*4);
                float4 xb = *(const float4*)(ss + pxB*68 + c4*4);
                #pragma unroll
                for (int cc = 0; cc < 4; cc++) {
                    float xac = (cc==0)?xa.x:(cc==1)?xa.y:(cc==2)?xa.z:xa.w;
                    float xbc = (cc==0)?xb.x:(cc==1)?xb.y:(cc==2)?xb.z:xb.w;
                    u64 xaP = pack2(xac, xac);
                    u64 xbP = pack2(xbc, xbc);
                    const float* wr = wk + (c4*4 + cc)*96 + j*12;
                    ulonglong2 wv0 = *(const ulonglong2*)(wr);
                    ulonglong2 wv1 = *(const ulonglong2*)(wr + 4);
                    accA[0] = ffma2(xaP, wv0.x, accA[0]);
                    accA[1] = ffma2(xaP, wv0.y, accA[1]);
                    accA[2] = ffma2(xaP, wv1.x, accA[2]);
                    accA[3] = ffma2(xaP, wv1.y, accA[3]);
                    accB[0] = ffma2(xbP, wv0.x, accB[0]);
                    accB[1] = ffma2(xbP, wv0.y, accB[1]);
                    accB[2] = ffma2(xbP, wv1.x, accB[2]);
                    accB[3] = ffma2(xbP, wv1.y, accB[3]);
                }
            }
            // -- gather(k+1) chunk: combine + STS
            if (k < 8) {
                #pragma unroll
                for (int p = 0; p < 2; p++) {
                    float cc0 = col ? gcf[p].y : gcf[p].x;
                    float cc1 = col ? gcf[p].w : gcf[p].z;
                    float4 t;
                    t.x = gq0[p].x*cc0 + gq1[p].x*cc1;
                    t.y = gq0[p].y*cc0 + gq1[p].y*cc1;
                    t.z = gq0[p].z*cc0 + gq1[p].z*cc1;
                    t.w = gq0[p].w*cc0 + gq1[p].w*cc1;
                    t.x += __shfl_xor_sync(0xffffffffu, t.x, 16);
                    t.y += __shfl_xor_sync(0xffffffffu, t.y, 16);
                    t.z += __shfl_xor_sync(0xffffffffu, t.z, 16);
                    t.w += __shfl_xor_sync(0xffffffffu, t.w, 16);
                    if (lane < 16) *(float4*)(gdst + (px0+p)*68 + lane*4) = t;
                }
            }
        }
        cp_wait0();
        __syncthreads();
    }

    // ---- epilogue: stage [o][px], coalesced NCHW store
    float* sOut = sm + C_SS0;
    #pragma unroll
    for (int q = 0; q < 4; q++) {
        int o = j*8 + 2*q;
        float lo, hi;
        unpack2(accA[q], lo, hi);
        sOut[o*128 + pxA] = lo;  sOut[(o+1)*128 + pxA] = hi;
        unpack2(accB[q], lo, hi);
        sOut[o*128 + pxB] = lo;  sOut[(o+1)*128 + pxB] = hi;
    }
    __syncthreads();
    float* ob = out + (size_t)b * COUT * HW + pxBase;
    for (int i = tid; i < 64*128; i += 512) {
        int o = i >> 7, p = i & 127;
        ob[(size_t)o*HW + p] = sOut[i];
    }
}

// ---------------------------------------------------------------------------
extern "C" void kernel_launch(void* const* d_in, const int* in_sizes, int n_in,
                              void* d_out, int out_size)
{
    const float* x      = (const float*)d_in[0];
    const float* w_off  = (const float*)d_in[1];
    const float* b_off  = (const float*)d_in[2];
    const float* weight = (const float*)d_in[3];
    const float* bias   = (const float*)d_in[4];
    float* out = (float*)d_out;

    static bool attr_done = false;
    if (!attr_done) {
        cudaFuncSetAttribute(dc_offsets, cudaFuncAttributeMaxDynamicSharedMemorySize,
                             B_SMEM_FLOATS * (int)sizeof(float));
        cudaFuncSetAttribute(dc_main, cudaFuncAttributeMaxDynamicSharedMemorySize,
                             C_SMEM_FLOATS * (int)sizeof(float));
        attr_done = true;
    }

    dc_transpose<<<Bdim * (HW/64), 256>>>(x);
    dc_wtrans   <<<(9*64*64 + 255)/256, 256>>>(weight, w_off);
    dc_offsets  <<<Bdim * Hdim, 384, B_SMEM_FLOATS * sizeof(float)>>>(b_off);
    dc_main     <<<Bdim * 72, 512, C_SMEM_FLOATS * sizeof(float)>>>(bias, out);
}

// round 6
// speedup vs baseline: 4.0846x; 1.9406x over previous
#include <cuda_runtime.h>
#include <math.h>
#include <stdint.h>

#define CIN   64
#define COUT  64
#define Hdim  96
#define Wdim  96
#define Bdim  8
#define HW    (Hdim*Wdim)     /* 9216  */
#define PTOT  (Bdim*HW)       /* 73728 */

// Scratch (no cudaMalloc allowed). g_xt padded +64 floats for column-overhang reads.
__device__ float g_xt [PTOT*CIN + 64];   // NHWC x: [(b*HW+h*96+w)*64 + c]
__device__ float g_pos[PTOT*9*3];        // per (pixel,k): ys, xs, mask
__device__ float g_wtm[9*4096];          // main weights, tf32 fragment-major per tap
__device__ float g_wo2[9*8*2*32*4];      // offset weights, tf32 fragment-major (18432 f)

// ---------------- helpers --------------------------------------------------
__device__ __forceinline__ void cp_async16(unsigned saddr, const void* g) {
    asm volatile("cp.async.cg.shared.global [%0], [%1], 16;" :: "r"(saddr), "l"(g));
}
__device__ __forceinline__ void cp_commit() { asm volatile("cp.async.commit_group;"); }
__device__ __forceinline__ void cp_wait0()  { asm volatile("cp.async.wait_group 0;"); }

__device__ __forceinline__ uint32_t tf32u(float x) {
    uint32_t r; asm("cvt.rna.tf32.f32 %0, %1;" : "=r"(r) : "f"(x)); return r;
}

// m16n8k8 tf32 MMA: D(16x8) += A(16x8,row) * B(8x8,col)
__device__ __forceinline__ void mma_tf32(float4& d, uint32_t a0, uint32_t a1,
                                         uint32_t a2, uint32_t a3,
                                         uint32_t b0, uint32_t b1) {
    asm volatile("mma.sync.aligned.m16n8k8.row.col.f32.tf32.tf32.f32 "
        "{%0,%1,%2,%3}, {%4,%5,%6,%7}, {%8,%9}, {%0,%1,%2,%3};"
        : "+f"(d.x), "+f"(d.y), "+f"(d.z), "+f"(d.w)
        : "r"(a0), "r"(a1), "r"(a2), "r"(a3), "r"(b0), "r"(b1));
}

// ---------------------------------------------------------------------------
// Kernel A: NCHW -> NHWC transpose of x
// ---------------------------------------------------------------------------
__global__ __launch_bounds__(256) void dc_transpose(const float* __restrict__ x)
{
    __shared__ float tile[64*65];
    int b  = blockIdx.x / 144;
    int s0 = (blockIdx.x % 144) * 64;
    const float* xb = x + (size_t)b * CIN * HW;
    for (int i = threadIdx.x; i < 64*64; i += 256) {
        int c = i >> 6, s = i & 63;
        tile[c*65 + s] = xb[(size_t)c*HW + s0 + s];
    }
    __syncthreads();
    float* xtb = g_xt + ((size_t)b*HW + s0) * 64;
    for (int i = threadIdx.x; i < 64*64; i += 256) {
        int s = i >> 6, c = i & 63;
        xtb[s*64 + c] = tile[c*65 + s];
    }
    if (blockIdx.x == 0 && threadIdx.x < 64)
        g_xt[(size_t)PTOT*CIN + threadIdx.x] = 0.f;
}

// ---------------------------------------------------------------------------
// Kernel A2: pack weights into tf32 fragment-major layouts.
// Main: per tap k, per (kstep s, ntile-pair ntp, lane): float4 =
//   {B(s,k0,nA), B(s,k0+4,nA), B(s,k0,nB), B(s,k0+4,nB)}
//   k0 = s*8+(lane&3), nA = 2ntp*8+(lane>>2), nB = nA+8.   [B(c,o) = w[o][c][k]]
// Offset: same scheme over kk taps with N padded 27->32 (2 ntp of 16 outputs).
// ---------------------------------------------------------------------------
__global__ __launch_bounds__(256) void dc_wtrans(const float* __restrict__ w,
                                                 const float* __restrict__ wo)
{
    int i = blockIdx.x * 256 + threadIdx.x;
    if (i < 9*64*64) {       // main weights: bijection (o,c,k) -> fragment slot
        int o = i / 576, r = i % 576, c = r / 9, k = r % 9;
        int s = c >> 3;
        int lane = (o & 7) * 4 + (c & 3);
        int nt = o >> 3, ntp = nt >> 1;
        int pos = ((nt & 1) << 1) | ((c >> 2) & 1);
        g_wtm[k*4096 + ((s*4 + ntp)*32 + lane)*4 + pos] = __uint_as_float(tf32u(w[i]));
    }
    if (i < 9*8*2*32*4) {    // offset weights
        int pos  = i & 3;
        int lane = (i >> 2) & 31;
        int rest = i >> 7;
        int ntp  = rest & 1;
        int s    = (rest >> 1) & 7;
        int kk   = rest >> 4;
        int m = (2*ntp + (pos >> 1))*8 + (lane >> 2);
        int c = s*8 + (lane & 3) + ((pos & 1) << 2);
        float v = (m < 27) ? wo[(size_t)m*576 + c*9 + kk] : 0.f;
        g_wo2[i] = __uint_as_float(tf32u(v));
    }
}

// ---------------------------------------------------------------------------
// Kernel B: offset conv (27 out-ch, 3x3) via mma.sync tf32 -> (ys, xs, mask)
// Block = one image row (96 px), 384 threads = 12 warps.
// Warp w: M-tile = px (w>>1)*16..+15, ntp = w&1 (outputs 16*ntp..16*ntp+15).
// ---------------------------------------------------------------------------
#define B_SP_SIZE  (3*98*68)                 /* 19992 f */
#define B_SB_OFF   B_SP_SIZE
#define B_SB_SIZE  (9*8*2*32*4)              /* 18432 f */
#define B_OM_OFF   (B_SB_OFF + B_SB_SIZE)
#define B_OM_SIZE  (96*28)
#define B_SMEM_FLOATS (B_OM_OFF + B_OM_SIZE) /* 41112 f = 164.4 KB */

__global__ __launch_bounds__(384, 1) void dc_offsets(const float* __restrict__ b_off)
{
    extern __shared__ float sm[];
    float* sP  = sm;                 // patch, tf32 bits
    float* sB  = sm + B_SB_OFF;      // B fragments
    float* sOm = sm + B_OM_OFF;
    unsigned sbBase = (unsigned)__cvta_generic_to_shared(sB);

    int tid = threadIdx.x;
    int b   = blockIdx.x / Hdim;
    int h   = blockIdx.x % Hdim;
    int gpixBase = b * HW + h * Wdim;

    // B fragments: straight cp.async copy
    for (int i = tid; i < B_SB_SIZE/4; i += 384)
        cp_async16(sbBase + (unsigned)i*16u, g_wo2 + i*4);
    cp_commit();

    // input patch: 3 rows x 98 cols (cols -1..96), tf32-converted, zero OOB
    const float* xtb = g_xt + (size_t)b * HW * 64;
    for (int r = 0; r < 3; r++) {
        int hh = h - 1 + r;
        bool rv = (hh >= 0) & (hh < Hdim);
        for (int i = tid; i < 98*64; i += 384) {
            int col = i >> 6, c = i & 63;
            int ww = col - 1;
            float v = 0.f;
            if (rv && ww >= 0 && ww < Wdim)
                v = xtb[((size_t)hh*Wdim + ww)*64 + c];
            sP[(r*98 + col)*68 + c] = __uint_as_float(tf32u(v));
        }
    }
    cp_wait0();
    __syncthreads();

    // GEMM: 96px x 32o x 576k
    int wid  = tid >> 5, lane = tid & 31;
    int g = lane >> 2, t = lane & 3;
    int px0 = (wid >> 1) * 16;
    int ntp = wid & 1;
    float4 d0 = make_float4(0.f,0.f,0.f,0.f);
    float4 d1 = make_float4(0.f,0.f,0.f,0.f);
    const uint32_t* P = (const uint32_t*)sP;

    #pragma unroll
    for (int kk = 0; kk < 9; kk++) {
        int ky = kk / 3, kx = kk % 3;
        const uint32_t* arow = P + (ky*98 + px0 + g + kx)*68;
        #pragma unroll
        for (int s = 0; s < 8; s++) {
            uint32_t a0 = arow[s*8 + t];
            uint32_t a1 = arow[8*68 + s*8 + t];
            uint32_t a2 = arow[s*8 + t + 4];
            uint32_t a3 = arow[8*68 + s*8 + t + 4];
            uint4 bq = *(const uint4*)(sB + (((kk*8 + s)*2 + ntp)*32 + lane)*4);
            mma_tf32(d0, a0,a1,a2,a3, bq.x, bq.y);
            mma_tf32(d1, a0,a1,a2,a3, bq.z, bq.w);
        }
    }

    // write om fragments (+bias), skip padded m>=27
    {
        int m0 = (2*ntp)*8 + 2*t;       // d0 -> m0, m0+1
        int m1 = (2*ntp + 1)*8 + 2*t;   // d1 -> m1, m1+1
        int pA = px0 + g, pB = px0 + g + 8;
        sOm[pA*28 + m0] = d0.x + __ldg(&b_off[m0]);
        sOm[pB*28 + m0] = d0.z + __ldg(&b_off[m0]);
        if (m0 + 1 < 27) {
            sOm[pA*28 + m0+1] = d0.y + __ldg(&b_off[m0+1]);
            sOm[pB*28 + m0+1] = d0.w + __ldg(&b_off[m0+1]);
        }
        if (m1 < 27) {
            sOm[pA*28 + m1] = d1.x + __ldg(&b_off[m1]);
            sOm[pB*28 + m1] = d1.z + __ldg(&b_off[m1]);
        }
        if (m1 + 1 < 27) {
            sOm[pA*28 + m1+1] = d1.y + __ldg(&b_off[m1+1]);
            sOm[pB*28 + m1+1] = d1.w + __ldg(&b_off[m1+1]);
        }
    }
    __syncthreads();

    // transform to (ys, xs, mask)
    for (int idx = tid; idx < 96*9; idx += 384) {
        int p2 = idx / 9, k = idx % 9;
        float dy = sOm[p2*28 + 2*k];
        float dx = sOm[p2*28 + 2*k + 1];
        float mv = sOm[p2*28 + 18 + k];
        float mask = 1.0f / (1.0f + __expf(-mv));
        int ky = k / 3, kx = k % 3;
        float ys = (float)(h - 1 + ky) + dy;
        float xs = (float)(p2 - 1 + kx) + dx;
        float* gp = g_pos + (size_t)(gpixBase + p2)*27 + k*3;
        gp[0] = ys; gp[1] = xs; gp[2] = mask;
    }
}

// ---------------------------------------------------------------------------
// Kernel C: fused bilinear sample + mma.sync tf32 GEMM.
// Block = 128 px, 256 threads = 8 warps; warp = 16 px M-tile x full N=64.
// Double-buffered sampled tile (tf32 bits) + double-buffered B fragments.
// ---------------------------------------------------------------------------
#define C_SS0    0
#define C_SS1    34816
#define C_SB0    69632
#define C_SB1    86016
#define C_COEF   102400
#define C_BASE   120832
#define C_SMEM_BYTES 130048

__global__ __launch_bounds__(256, 1)
void dc_main(const float* __restrict__ bias, float* __restrict__ out)
{
    extern __shared__ char smc[];
    unsigned smem_base = (unsigned)__cvta_generic_to_shared(smc);
    float4* sCoef = (float4*)(smc + C_COEF);
    int2*   sBase = (int2*)  (smc + C_BASE);

    int tid = threadIdx.x;
    int wid = tid >> 5, lane = tid & 31;
    int g = lane >> 2, t = lane & 3;
    int b      = blockIdx.x / 72;
    int pxBase = (blockIdx.x % 72) * 128;
    int gpixBase = b * HW + pxBase;
    const float* xtb = g_xt + (size_t)b * HW * 64;
    int px0w = wid * 16;

    // meta precompute: per (px,k) bilinear coefs (mask folded) + clamped bases
    for (int i = tid; i < 1152; i += 256) {
        int px = i / 9, k = i % 9;
        const float* gp = g_pos + (size_t)(gpixBase + px)*27 + k*3;
        float ys = gp[0], xs = gp[1], mk = gp[2];
        float y0f = floorf(ys), x0f = floorf(xs);
        float ty = ys - y0f, tx = xs - x0f;
        int iy0 = (int)y0f, ix0 = (int)x0f;
        float wy0 = (iy0 >= 0 && iy0 <= Hdim-1) ? (1.f - ty) : 0.f;
        float wy1 = (iy0+1 >= 0 && iy0+1 <= Hdim-1) ? ty : 0.f;
        float wx0 = (ix0 >= 0 && ix0 <= Wdim-1) ? (1.f - tx) : 0.f;
        float wx1 = (ix0+1 >= 0 && ix0+1 <= Wdim-1) ? tx : 0.f;
        int bx = min(max(ix0, 0), Wdim-1);
        float cx0 = (ix0 == bx) ? wx0 : ((ix0 + 1 == bx) ? wx1 : 0.f);
        float cx1 = (ix0 == bx) ? wx1 : 0.f;
        int cy0 = min(max(iy0,   0), Hdim-1);
        int cy1 = min(max(iy0+1, 0), Hdim-1);
        float4 cf;
        cf.x = wy0*cx0*mk;  cf.y = wy0*cx1*mk;
        cf.z = wy1*cx0*mk;  cf.w = wy1*cx1*mk;
        sCoef[k*128 + px] = cf;
        sBase[k*128 + px] = make_int2((cy0*Wdim + bx)*64, (cy1*Wdim + bx)*64);
    }

    float4 acc[8];
    #pragma unroll
    for (int nt = 0; nt < 8; nt++) acc[nt] = make_float4(0.f,0.f,0.f,0.f);

    // prologue: B(0) via cp.async; gather tap 0 -> sS0
    for (int i = tid; i < 1024; i += 256)
        cp_async16(smem_base + C_SB0 + (unsigned)i*16u, g_wtm + i*4);
    cp_commit();
    __syncthreads();   // meta ready
    {
        float* dst = (float*)(smc + C_SS0);
        #pragma unroll
        for (int p = 0; p < 16; p++) {
            int px = px0w + p;
            int2 bs = sBase[px];          // k=0
            float4 cf = sCoef[px];
            float4 q0 = *(const float4*)(xtb + bs.x + lane*4);
            float4 q1 = *(const float4*)(xtb + bs.y + lane*4);
            float c0 = (lane & 16) ? cf.y : cf.x;
            float c1 = (lane & 16) ? cf.w : cf.z;
            float t0 = q0.x*c0 + q1.x*c1;
            float t1 = q0.y*c0 + q1.y*c1;
            float t2 = q0.z*c0 + q1.z*c1;
            float t3 = q0.w*c0 + q1.w*c1;
            t0 += __shfl_xor_sync(0xffffffffu, t0, 16);
            t1 += __shfl_xor_sync(0xffffffffu, t1, 16);
            t2 += __shfl_xor_sync(0xffffffffu, t2, 16);
            t3 += __shfl_xor_sync(0xffffffffu, t3, 16);
            if (lane < 16) {
                uint32_t r0 = tf32u(t0), r1 = tf32u(t1), r2 = tf32u(t2), r3 = tf32u(t3);
                unsigned addr = smem_base + C_SS0 + (unsigned)(px*68 + lane*4)*4u;
                asm volatile("st.shared.v4.b32 [%0], {%1, %2, %3, %4};"
                             :: "r"(addr), "r"(r0), "r"(r1), "r"(r2), "r"(r3));
            }
        }
    }
    cp_wait0();
    __syncthreads();

    // main loop over taps
    for (int k = 0; k < 9; k++) {
        int cur = k & 1, nxt = cur ^ 1;
        if (k < 8) {   // stream B(k+1)
            unsigned dstB = smem_base + (nxt ? C_SB1 : C_SB0);
            const float* srcB = g_wtm + (k+1)*4096;
            for (int i = tid; i < 1024; i += 256)
                cp_async16(dstB + (unsigned)i*16u, srcB + i*4);
            cp_commit();
        }
        const uint32_t* ssb = (const uint32_t*)(smc + (cur ? C_SS1 : C_SS0));
        const float*    sBc = (const float*)(smc + (cur ? C_SB1 : C_SB0));
        unsigned gdst = smem_base + (nxt ? C_SS1 : C_SS0);
        const uint32_t* arow = ssb + (px0w + g)*68;

        #pragma unroll
        for (int ch = 0; ch < 4; ch++) {
            // gather(k+1) chunk: 4 px, issue LDGs early
            float4 gq0[4], gq1[4], gcf[4];
            int pg0 = px0w + ch*4;
            if (k < 8) {
                #pragma unroll
                for (int p = 0; p < 4; p++) {
                    int mi = (k+1)*128 + pg0 + p;
                    int2 bs = sBase[mi];
                    gcf[p] = sCoef[mi];
                    gq0[p] = *(const float4*)(xtb + bs.x + lane*4);
                    gq1[p] = *(const float4*)(xtb + bs.y + lane*4);
                }
            }
            // GEMM: ksteps s = 2ch, 2ch+1
            #pragma unroll
            for (int si = 0; si < 2; si++) {
                int s = ch*2 + si;
                uint32_t a0 = arow[s*8 + t];
                uint32_t a1 = arow[8*68 + s*8 + t];
                uint32_t a2 = arow[s*8 + t + 4];
                uint32_t a3 = arow[8*68 + s*8 + t + 4];
                #pragma unroll
                for (int ntp = 0; ntp < 4; ntp++) {
                    uint4 bq = *(const uint4*)(sBc + ((s*4 + ntp)*32 + lane)*4);
                    mma_tf32(acc[2*ntp  ], a0,a1,a2,a3, bq.x, bq.y);
                    mma_tf32(acc[2*ntp+1], a0,a1,a2,a3, bq.z, bq.w);
                }
            }
            // gather(k+1) chunk: combine + cvt + STS
            if (k < 8) {
                #pragma unroll
                for (int p = 0; p < 4; p++) {
                    float c0 = (lane & 16) ? gcf[p].y : gcf[p].x;
                    float c1 = (lane & 16) ? gcf[p].w : gcf[p].z;
                    float t0 = gq0[p].x*c0 + gq1[p].x*c1;
                    float t1 = gq0[p].y*c0 + gq1[p].y*c1;
                    float t2 = gq0[p].z*c0 + gq1[p].z*c1;
                    float t3 = gq0[p].w*c0 + gq1[p].w*c1;
                    t0 += __shfl_xor_sync(0xffffffffu, t0, 16);
                    t1 += __shfl_xor_sync(0xffffffffu, t1, 16);
                    t2 += __shfl_xor_sync(0xffffffffu, t2, 16);
                    t3 += __shfl_xor_sync(0xffffffffu, t3, 16);
                    if (lane < 16) {
                        uint32_t r0 = tf32u(t0), r1 = tf32u(t1),
                                 r2 = tf32u(t2), r3 = tf32u(t3);
                        unsigned addr = gdst + (unsigned)((pg0+p)*68 + lane*4)*4u;
                        asm volatile("st.shared.v4.b32 [%0], {%1, %2, %3, %4};"
                                     :: "r"(addr), "r"(r0), "r"(r1), "r"(r2), "r"(r3));
                    }
                }
            }
        }
        cp_wait0();
        __syncthreads();
    }

    // epilogue: fragments -> sOut[o][px] (stride 132, conflict-free), then NCHW
    float* sOut = (float*)smc;   // reuses sS0 region (64*132*4 = 33792 B)
    #pragma unroll
    for (int nt = 0; nt < 8; nt++) {
        int o = nt*8 + 2*t;
        int pA = px0w + g, pB = px0w + g + 8;
        sOut[o*132 + pA]     = acc[nt].x;
        sOut[(o+1)*132 + pA] = acc[nt].y;
        sOut[o*132 + pB]     = acc[nt].z;
        sOut[(o+1)*132 + pB] = acc[nt].w;
    }
    __syncthreads();
    float* ob = out + (size_t)b * COUT * HW + pxBase;
    for (int i = tid; i < 64*128; i += 256) {
        int o = i >> 7, p = i & 127;
        ob[(size_t)o*HW + p] = sOut[o*132 + p] + __ldg(&bias[o]);
    }
}

// ---------------------------------------------------------------------------
extern "C" void kernel_launch(void* const* d_in, const int* in_sizes, int n_in,
                              void* d_out, int out_size)
{
    const float* x      = (const float*)d_in[0];
    const float* w_off  = (const float*)d_in[1];
    const float* b_off  = (const float*)d_in[2];
    const float* weight = (const float*)d_in[3];
    const float* bias   = (const float*)d_in[4];
    float* out = (float*)d_out;

    static bool attr_done = false;
    if (!attr_done) {
        cudaFuncSetAttribute(dc_offsets, cudaFuncAttributeMaxDynamicSharedMemorySize,
                             B_SMEM_FLOATS * (int)sizeof(float));
        cudaFuncSetAttribute(dc_main, cudaFuncAttributeMaxDynamicSharedMemorySize,
                             C_SMEM_BYTES);
        attr_done = true;
    }

    dc_transpose<<<Bdim * (HW/64), 256>>>(x);
    dc_wtrans   <<<(9*64*64 + 255)/256, 256>>>(weight, w_off);
    dc_offsets  <<<Bdim * Hdim, 384, B_SMEM_FLOATS * sizeof(float)>>>(b_off);
    dc_main     <<<Bdim * 72, 256, C_SMEM_BYTES>>>(bias, out);
}

// round 7
// speedup vs baseline: 4.8980x; 1.1991x over previous
#include <cuda_runtime.h>
#include <math.h>
#include <stdint.h>

#define CIN   64
#define COUT  64
#define Hdim  96
#define Wdim  96
#define Bdim  8
#define HW    (Hdim*Wdim)     /* 9216  */
#define PTOT  (Bdim*HW)       /* 73728 */

// Scratch (no cudaMalloc allowed). g_xt padded +64 floats for column-overhang reads.
__device__ float g_xt [PTOT*CIN + 64];   // NHWC x: [(b*HW+h*96+w)*64 + c]
__device__ float g_pos[PTOT*9*3];        // per (pixel,k): ys, xs, mask
__device__ float g_wtm[9*4096];          // main weights, tf32 fragment-major per tap
__device__ float g_wo2[9*8*2*32*4];      // offset weights, tf32 fragment-major (18432 f)

// ---------------- helpers --------------------------------------------------
__device__ __forceinline__ void cp_async16(unsigned saddr, const void* g) {
    asm volatile("cp.async.cg.shared.global [%0], [%1], 16;" :: "r"(saddr), "l"(g));
}
__device__ __forceinline__ void cp_commit() { asm volatile("cp.async.commit_group;"); }
__device__ __forceinline__ void cp_wait0()  { asm volatile("cp.async.wait_group 0;"); }

__device__ __forceinline__ uint32_t tf32u(float x) {
    uint32_t r; asm("cvt.rna.tf32.f32 %0, %1;" : "=r"(r) : "f"(x)); return r;
}

// m16n8k8 tf32 MMA: D(16x8) += A(16x8,row) * B(8x8,col)
__device__ __forceinline__ void mma_tf32(float4& d, uint32_t a0, uint32_t a1,
                                         uint32_t a2, uint32_t a3,
                                         uint32_t b0, uint32_t b1) {
    asm volatile("mma.sync.aligned.m16n8k8.row.col.f32.tf32.tf32.f32 "
        "{%0,%1,%2,%3}, {%4,%5,%6,%7}, {%8,%9}, {%0,%1,%2,%3};"
        : "+f"(d.x), "+f"(d.y), "+f"(d.z), "+f"(d.w)
        : "r"(a0), "r"(a1), "r"(a2), "r"(a3), "r"(b0), "r"(b1));
}

// ---------------------------------------------------------------------------
// Kernel A: NCHW -> NHWC transpose of x
// ---------------------------------------------------------------------------
__global__ __launch_bounds__(256) void dc_transpose(const float* __restrict__ x)
{
    __shared__ float tile[64*65];
    int b  = blockIdx.x / 144;
    int s0 = (blockIdx.x % 144) * 64;
    const float* xb = x + (size_t)b * CIN * HW;
    for (int i = threadIdx.x; i < 64*64; i += 256) {
        int c = i >> 6, s = i & 63;
        tile[c*65 + s] = xb[(size_t)c*HW + s0 + s];
    }
    __syncthreads();
    float* xtb = g_xt + ((size_t)b*HW + s0) * 64;
    for (int i = threadIdx.x; i < 64*64; i += 256) {
        int s = i >> 6, c = i & 63;
        xtb[s*64 + c] = tile[c*65 + s];
    }
    if (blockIdx.x == 0 && threadIdx.x < 64)
        g_xt[(size_t)PTOT*CIN + threadIdx.x] = 0.f;
}

// ---------------------------------------------------------------------------
// Kernel A2: pack weights into tf32 fragment-major layouts.
// ---------------------------------------------------------------------------
__global__ __launch_bounds__(256) void dc_wtrans(const float* __restrict__ w,
                                                 const float* __restrict__ wo)
{
    int i = blockIdx.x * 256 + threadIdx.x;
    if (i < 9*64*64) {       // main weights: bijection (o,c,k) -> fragment slot
        int o = i / 576, r = i % 576, c = r / 9, k = r % 9;
        int s = c >> 3;
        int lane = (o & 7) * 4 + (c & 3);
        int nt = o >> 3, ntp = nt >> 1;
        int pos = ((nt & 1) << 1) | ((c >> 2) & 1);
        g_wtm[k*4096 + ((s*4 + ntp)*32 + lane)*4 + pos] = __uint_as_float(tf32u(w[i]));
    }
    if (i < 9*8*2*32*4) {    // offset weights
        int pos  = i & 3;
        int lane = (i >> 2) & 31;
        int rest = i >> 7;
        int ntp  = rest & 1;
        int s    = (rest >> 1) & 7;
        int kk   = rest >> 4;
        int m = (2*ntp + (pos >> 1))*8 + (lane >> 2);
        int c = s*8 + (lane & 3) + ((pos & 1) << 2);
        float v = (m < 27) ? wo[(size_t)m*576 + c*9 + kk] : 0.f;
        g_wo2[i] = __uint_as_float(tf32u(v));
    }
}

// ---------------------------------------------------------------------------
// Kernel B: offset conv (27 out-ch, 3x3) via mma.sync tf32 -> (ys, xs, mask)
// ---------------------------------------------------------------------------
#define B_SP_SIZE  (3*98*68)                 /* 19992 f */
#define B_SB_OFF   B_SP_SIZE
#define B_SB_SIZE  (9*8*2*32*4)              /* 18432 f */
#define B_OM_OFF   (B_SB_OFF + B_SB_SIZE)
#define B_OM_SIZE  (96*28)
#define B_SMEM_FLOATS (B_OM_OFF + B_OM_SIZE) /* 41112 f = 164.4 KB */

__global__ __launch_bounds__(384, 1) void dc_offsets(const float* __restrict__ b_off)
{
    extern __shared__ float sm[];
    float* sP  = sm;
    float* sB  = sm + B_SB_OFF;
    float* sOm = sm + B_OM_OFF;
    unsigned sbBase = (unsigned)__cvta_generic_to_shared(sB);

    int tid = threadIdx.x;
    int b   = blockIdx.x / Hdim;
    int h   = blockIdx.x % Hdim;
    int gpixBase = b * HW + h * Wdim;

    for (int i = tid; i < B_SB_SIZE/4; i += 384)
        cp_async16(sbBase + (unsigned)i*16u, g_wo2 + i*4);
    cp_commit();

    const float* xtb = g_xt + (size_t)b * HW * 64;
    for (int r = 0; r < 3; r++) {
        int hh = h - 1 + r;
        bool rv = (hh >= 0) & (hh < Hdim);
        for (int i = tid; i < 98*64; i += 384) {
            int col = i >> 6, c = i & 63;
            int ww = col - 1;
            float v = 0.f;
            if (rv && ww >= 0 && ww < Wdim)
                v = xtb[((size_t)hh*Wdim + ww)*64 + c];
            sP[(r*98 + col)*68 + c] = __uint_as_float(tf32u(v));
        }
    }
    cp_wait0();
    __syncthreads();

    int wid  = tid >> 5, lane = tid & 31;
    int g = lane >> 2, t = lane & 3;
    int px0 = (wid >> 1) * 16;
    int ntp = wid & 1;
    float4 d0 = make_float4(0.f,0.f,0.f,0.f);
    float4 d1 = make_float4(0.f,0.f,0.f,0.f);
    const uint32_t* P = (const uint32_t*)sP;

    #pragma unroll
    for (int kk = 0; kk < 9; kk++) {
        int ky = kk / 3, kx = kk % 3;
        const uint32_t* arow = P + (ky*98 + px0 + g + kx)*68;
        #pragma unroll
        for (int s = 0; s < 8; s++) {
            uint32_t a0 = arow[s*8 + t];
            uint32_t a1 = arow[8*68 + s*8 + t];
            uint32_t a2 = arow[s*8 + t + 4];
            uint32_t a3 = arow[8*68 + s*8 + t + 4];
            uint4 bq = *(const uint4*)(sB + (((kk*8 + s)*2 + ntp)*32 + lane)*4);
            mma_tf32(d0, a0,a1,a2,a3, bq.x, bq.y);
            mma_tf32(d1, a0,a1,a2,a3, bq.z, bq.w);
        }
    }

    {
        int m0 = (2*ntp)*8 + 2*t;
        int m1 = (2*ntp + 1)*8 + 2*t;
        int pA = px0 + g, pB = px0 + g + 8;
        sOm[pA*28 + m0] = d0.x + __ldg(&b_off[m0]);
        sOm[pB*28 + m0] = d0.z + __ldg(&b_off[m0]);
        if (m0 + 1 < 27) {
            sOm[pA*28 + m0+1] = d0.y + __ldg(&b_off[m0+1]);
            sOm[pB*28 + m0+1] = d0.w + __ldg(&b_off[m0+1]);
        }
        if (m1 < 27) {
            sOm[pA*28 + m1] = d1.x + __ldg(&b_off[m1]);
            sOm[pB*28 + m1] = d1.z + __ldg(&b_off[m1]);
        }
        if (m1 + 1 < 27) {
            sOm[pA*28 + m1+1] = d1.y + __ldg(&b_off[m1+1]);
            sOm[pB*28 + m1+1] = d1.w + __ldg(&b_off[m1+1]);
        }
    }
    __syncthreads();

    for (int idx = tid; idx < 96*9; idx += 384) {
        int p2 = idx / 9, k = idx % 9;
        float dy = sOm[p2*28 + 2*k];
        float dx = sOm[p2*28 + 2*k + 1];
        float mv = sOm[p2*28 + 18 + k];
        float mask = 1.0f / (1.0f + __expf(-mv));
        int ky = k / 3, kx = k % 3;
        float ys = (float)(h - 1 + ky) + dy;
        float xs = (float)(p2 - 1 + kx) + dx;
        float* gp = g_pos + (size_t)(gpixBase + p2)*27 + k*3;
        gp[0] = ys; gp[1] = xs; gp[2] = mask;
    }
}

// ---------------------------------------------------------------------------
// Kernel C: fused bilinear sample + mma.sync tf32 GEMM. 2 blocks/SM.
// Block = 128 px, 256 threads = 8 warps; warp = 16 px M-tile x full N=64.
// Double-buffered: sampled tile, B fragments, and 2-tap meta (pipelined).
// smem: sS 2x34816, sB 2x16384, coef 2x128xfloat4, base 2x128xint2 = 108544 B
// ---------------------------------------------------------------------------
#define C_SS0    0
#define C_SS1    34816
#define C_SB0    69632
#define C_SB1    86016
#define C_COEF   102400
#define C_BASE   106496
#define C_SMEM_BYTES 108544

__global__ __launch_bounds__(256, 2)
void dc_main(const float* __restrict__ bias, float* __restrict__ out)
{
    extern __shared__ char smc[];
    unsigned smem_base = (unsigned)__cvta_generic_to_shared(smc);
    float4* sCoef = (float4*)(smc + C_COEF);   // [buf][px] buf = tap&1
    int2*   sBase = (int2*)  (smc + C_BASE);

    int tid = threadIdx.x;
    int wid = tid >> 5, lane = tid & 31;
    int g = lane >> 2, t = lane & 3;
    int b      = blockIdx.x / 72;
    int pxBase = (blockIdx.x % 72) * 128;
    int gpixBase = b * HW + pxBase;
    const float* xtb = g_xt + (size_t)b * HW * 64;
    int px0w = wid * 16;

    float4 acc[8];
    #pragma unroll
    for (int nt = 0; nt < 8; nt++) acc[nt] = make_float4(0.f,0.f,0.f,0.f);

    // meta compute for (tap kk, pixel px) into buffer kk&1
    auto meta1 = [&](int kk, int px) {
        const float* gp = g_pos + (size_t)(gpixBase + px)*27 + kk*3;
        float ys = gp[0], xs = gp[1], mk = gp[2];
        float y0f = floorf(ys), x0f = floorf(xs);
        float ty = ys - y0f, tx = xs - x0f;
        int iy0 = (int)y0f, ix0 = (int)x0f;
        float wy0 = (iy0 >= 0 && iy0 <= Hdim-1) ? (1.f - ty) : 0.f;
        float wy1 = (iy0+1 >= 0 && iy0+1 <= Hdim-1) ? ty : 0.f;
        float wx0 = (ix0 >= 0 && ix0 <= Wdim-1) ? (1.f - tx) : 0.f;
        float wx1 = (ix0+1 >= 0 && ix0+1 <= Wdim-1) ? tx : 0.f;
        int bx = min(max(ix0, 0), Wdim-1);
        float cx0 = (ix0 == bx) ? wx0 : ((ix0 + 1 == bx) ? wx1 : 0.f);
        float cx1 = (ix0 == bx) ? wx1 : 0.f;
        int cy0 = min(max(iy0,   0), Hdim-1);
        int cy1 = min(max(iy0+1, 0), Hdim-1);
        float4 cf;
        cf.x = wy0*cx0*mk;  cf.y = wy0*cx1*mk;
        cf.z = wy1*cx0*mk;  cf.w = wy1*cx1*mk;
        sCoef[(kk&1)*128 + px] = cf;
        sBase[(kk&1)*128 + px] = make_int2((cy0*Wdim + bx)*64, (cy1*Wdim + bx)*64);
    };

    // ---- prologue: B(0) cp.async; meta(0), meta(1); gather(0)
    for (int i = tid; i < 1024; i += 256)
        cp_async16(smem_base + C_SB0 + (unsigned)i*16u, g_wtm + i*4);
    cp_commit();
    {   // 256 entries (2 taps x 128 px), one per thread
        int kk = tid >> 7, px = tid & 127;
        meta1(kk, px);
    }
    __syncthreads();
    {
        #pragma unroll
        for (int p = 0; p < 16; p++) {
            int px = px0w + p;
            int2 bs = sBase[px];          // buf0 = tap0
            float4 cf = sCoef[px];
            float4 q0 = *(const float4*)(xtb + bs.x + lane*4);
            float4 q1 = *(const float4*)(xtb + bs.y + lane*4);
            float c0 = (lane & 16) ? cf.y : cf.x;
            float c1 = (lane & 16) ? cf.w : cf.z;
            float t0 = q0.x*c0 + q1.x*c1;
            float t1 = q0.y*c0 + q1.y*c1;
            float t2 = q0.z*c0 + q1.z*c1;
            float t3 = q0.w*c0 + q1.w*c1;
            t0 += __shfl_xor_sync(0xffffffffu, t0, 16);
            t1 += __shfl_xor_sync(0xffffffffu, t1, 16);
            t2 += __shfl_xor_sync(0xffffffffu, t2, 16);
            t3 += __shfl_xor_sync(0xffffffffu, t3, 16);
            if (lane < 16) {
                uint32_t r0 = tf32u(t0), r1 = tf32u(t1), r2 = tf32u(t2), r3 = tf32u(t3);
                unsigned addr = smem_base + C_SS0 + (unsigned)(px*68 + lane*4)*4u;
                asm volatile("st.shared.v4.b32 [%0], {%1, %2, %3, %4};"
                             :: "r"(addr), "r"(r0), "r"(r1), "r"(r2), "r"(r3));
            }
        }
    }
    cp_wait0();
    __syncthreads();

    // ---- main loop over taps
    for (int k = 0; k < 9; k++) {
        int cur = k & 1, nxt = cur ^ 1;
        if (k < 8) {   // stream B(k+1)
            unsigned dstB = smem_base + (nxt ? C_SB1 : C_SB0);
            const float* srcB = g_wtm + (k+1)*4096;
            for (int i = tid; i < 1024; i += 256)
                cp_async16(dstB + (unsigned)i*16u, srcB + i*4);
            cp_commit();
        }
        // pipeline meta(k+2) into buffer (k+2)&1 == k&1 (meta(k) already consumed)
        if (k < 7 && tid < 128) meta1(k+2, tid);

        const uint32_t* ssb = (const uint32_t*)(smc + (cur ? C_SS1 : C_SS0));
        const float*    sBc = (const float*)(smc + (cur ? C_SB1 : C_SB0));
        unsigned gdst = smem_base + (nxt ? C_SS1 : C_SS0);
        const uint32_t* arow = ssb + (px0w + g)*68;
        const float4* cfb = sCoef + nxt*128;   // meta(k+1)
        const int2*   bsb = sBase + nxt*128;

        #pragma unroll
        for (int ch = 0; ch < 8; ch++) {
            // gather(k+1) chunk: 2 px, issue LDGs early
            float4 gq0[2], gq1[2], gcf[2];
            int pg0 = px0w + ch*2;
            if (k < 8) {
                #pragma unroll
                for (int p = 0; p < 2; p++) {
                    int2 bs = bsb[pg0 + p];
                    gcf[p] = cfb[pg0 + p];
                    gq0[p] = *(const float4*)(xtb + bs.x + lane*4);
                    gq1[p] = *(const float4*)(xtb + bs.y + lane*4);
                }
            }
            // GEMM: kstep s = ch
            {
                int s = ch;
                uint32_t a0 = arow[s*8 + t];
                uint32_t a1 = arow[8*68 + s*8 + t];
                uint32_t a2 = arow[s*8 + t + 4];
                uint32_t a3 = arow[8*68 + s*8 + t + 4];
                #pragma unroll
                for (int ntp = 0; ntp < 4; ntp++) {
                    uint4 bq = *(const uint4*)(sBc + ((s*4 + ntp)*32 + lane)*4);
                    mma_tf32(acc[2*ntp  ], a0,a1,a2,a3, bq.x, bq.y);
                    mma_tf32(acc[2*ntp+1], a0,a1,a2,a3, bq.z, bq.w);
                }
            }
            // gather(k+1) chunk: combine + cvt + STS
            if (k < 8) {
                #pragma unroll
                for (int p = 0; p < 2; p++) {
                    float c0 = (lane & 16) ? gcf[p].y : gcf[p].x;
                    float c1 = (lane & 16) ? gcf[p].w : gcf[p].z;
                    float t0 = gq0[p].x*c0 + gq1[p].x*c1;
                    float t1 = gq0[p].y*c0 + gq1[p].y*c1;
                    float t2 = gq0[p].z*c0 + gq1[p].z*c1;
                    float t3 = gq0[p].w*c0 + gq1[p].w*c1;
                    t0 += __shfl_xor_sync(0xffffffffu, t0, 16);
                    t1 += __shfl_xor_sync(0xffffffffu, t1, 16);
                    t2 += __shfl_xor_sync(0xffffffffu, t2, 16);
                    t3 += __shfl_xor_sync(0xffffffffu, t3, 16);
                    if (lane < 16) {
                        uint32_t r0 = tf32u(t0), r1 = tf32u(t1),
                                 r2 = tf32u(t2), r3 = tf32u(t3);
                        unsigned addr = gdst + (unsigned)((pg0+p)*68 + lane*4)*4u;
                        asm volatile("st.shared.v4.b32 [%0], {%1, %2, %3, %4};"
                                     :: "r"(addr), "r"(r0), "r"(r1), "r"(r2), "r"(r3));
                    }
                }
            }
        }
        cp_wait0();
        __syncthreads();
    }

    // ---- epilogue: fragments -> sOut[o][px] (stride 132), then NCHW store
    float* sOut = (float*)smc;
    #pragma unroll
    for (int nt = 0; nt < 8; nt++) {
        int o = nt*8 + 2*t;
        int pA = px0w + g, pB = px0w + g + 8;
        sOut[o*132 + pA]     = acc[nt].x;
        sOut[(o+1)*132 + pA] = acc[nt].y;
        sOut[o*132 + pB]     = acc[nt].z;
        sOut[(o+1)*132 + pB] = acc[nt].w;
    }
    __syncthreads();
    float* ob = out + (size_t)b * COUT * HW + pxBase;
    for (int i = tid; i < 64*128; i += 256) {
        int o = i >> 7, p = i & 127;
        ob[(size_t)o*HW + p] = sOut[o*132 + p] + __ldg(&bias[o]);
    }
}

// ---------------------------------------------------------------------------
extern "C" void kernel_launch(void* const* d_in, const int* in_sizes, int n_in,
                              void* d_out, int out_size)
{
    const float* x      = (const float*)d_in[0];
    const float* w_off  = (const float*)d_in[1];
    const float* b_off  = (const float*)d_in[2];
    const float* weight = (const float*)d_in[3];
    const float* bias   = (const float*)d_in[4];
    float* out = (float*)d_out;

    static bool attr_done = false;
    if (!attr_done) {
        cudaFuncSetAttribute(dc_offsets, cudaFuncAttributeMaxDynamicSharedMemorySize,
                             B_SMEM_FLOATS * (int)sizeof(float));
        cudaFuncSetAttribute(dc_main, cudaFuncAttributeMaxDynamicSharedMemorySize,
                             C_SMEM_BYTES);
        attr_done = true;
    }

    dc_transpose<<<Bdim * (HW/64), 256>>>(x);
    dc_wtrans   <<<(9*64*64 + 255)/256, 256>>>(weight, w_off);
    dc_offsets  <<<Bdim * Hdim, 384, B_SMEM_FLOATS * sizeof(float)>>>(b_off);
    dc_main     <<<Bdim * 72, 256, C_SMEM_BYTES>>>(bias, out);
}

// round 8
// speedup vs baseline: 5.4461x; 1.1119x over previous
#include <cuda_runtime.h>
#include <math.h>
#include <stdint.h>

#define CIN   64
#define COUT  64
#define Hdim  96
#define Wdim  96
#define Bdim  8
#define HW    (Hdim*Wdim)     /* 9216  */
#define PTOT  (Bdim*HW)       /* 73728 */

// Scratch (no cudaMalloc allowed). g_xt padded +64 floats for column-overhang reads.
__device__ float g_xt [PTOT*CIN + 64];   // NHWC x: [(b*HW+h*96+w)*64 + c]
__device__ float g_pos[PTOT*9*3];        // per (pixel,k): ys, xs, mask
__device__ float g_wtm[9*4096];          // main weights, tf32 fragment-major per tap
__device__ float g_wo2[9*8*2*32*4];      // offset weights, tf32 fragment-major (18432 f)

// ---------------- helpers --------------------------------------------------
__device__ __forceinline__ void cp_async16(unsigned saddr, const void* g) {
    asm volatile("cp.async.cg.shared.global [%0], [%1], 16;" :: "r"(saddr), "l"(g));
}
__device__ __forceinline__ void cp_commit() { asm volatile("cp.async.commit_group;"); }
__device__ __forceinline__ void cp_wait0()  { asm volatile("cp.async.wait_group 0;"); }

__device__ __forceinline__ uint32_t tf32u(float x) {
    uint32_t r; asm("cvt.rna.tf32.f32 %0, %1;" : "=r"(r) : "f"(x)); return r;
}

// m16n8k8 tf32 MMA: D(16x8) += A(16x8,row) * B(8x8,col)
__device__ __forceinline__ void mma_tf32(float4& d, uint32_t a0, uint32_t a1,
                                         uint32_t a2, uint32_t a3,
                                         uint32_t b0, uint32_t b1) {
    asm volatile("mma.sync.aligned.m16n8k8.row.col.f32.tf32.tf32.f32 "
        "{%0,%1,%2,%3}, {%4,%5,%6,%7}, {%8,%9}, {%0,%1,%2,%3};"
        : "+f"(d.x), "+f"(d.y), "+f"(d.z), "+f"(d.w)
        : "r"(a0), "r"(a1), "r"(a2), "r"(a3), "r"(b0), "r"(b1));
}

// ---------------------------------------------------------------------------
// Kernel A: NCHW -> NHWC transpose of x
// ---------------------------------------------------------------------------
__global__ __launch_bounds__(256) void dc_transpose(const float* __restrict__ x)
{
    __shared__ float tile[64*65];
    int b  = blockIdx.x / 144;
    int s0 = (blockIdx.x % 144) * 64;
    const float* xb = x + (size_t)b * CIN * HW;
    for (int i = threadIdx.x; i < 64*64; i += 256) {
        int c = i >> 6, s = i & 63;
        tile[c*65 + s] = xb[(size_t)c*HW + s0 + s];
    }
    __syncthreads();
    float* xtb = g_xt + ((size_t)b*HW + s0) * 64;
    for (int i = threadIdx.x; i < 64*64; i += 256) {
        int s = i >> 6, c = i & 63;
        xtb[s*64 + c] = tile[c*65 + s];
    }
    if (blockIdx.x == 0 && threadIdx.x < 64)
        g_xt[(size_t)PTOT*CIN + threadIdx.x] = 0.f;
}

// ---------------------------------------------------------------------------
// Kernel A2: pack weights into tf32 fragment-major layouts.
// ---------------------------------------------------------------------------
__global__ __launch_bounds__(256) void dc_wtrans(const float* __restrict__ w,
                                                 const float* __restrict__ wo)
{
    int i = blockIdx.x * 256 + threadIdx.x;
    if (i < 9*64*64) {       // main weights: bijection (o,c,k) -> fragment slot
        int o = i / 576, r = i % 576, c = r / 9, k = r % 9;
        int s = c >> 3;
        int lane = (o & 7) * 4 + (c & 3);
        int nt = o >> 3, ntp = nt >> 1;
        int pos = ((nt & 1) << 1) | ((c >> 2) & 1);
        g_wtm[k*4096 + ((s*4 + ntp)*32 + lane)*4 + pos] = __uint_as_float(tf32u(w[i]));
    }
    if (i < 9*8*2*32*4) {    // offset weights
        int pos  = i & 3;
        int lane = (i >> 2) & 31;
        int rest = i >> 7;
        int ntp  = rest & 1;
        int s    = (rest >> 1) & 7;
        int kk   = rest >> 4;
        int m = (2*ntp + (pos >> 1))*8 + (lane >> 2);
        int c = s*8 + (lane & 3) + ((pos & 1) << 2);
        float v = (m < 27) ? wo[(size_t)m*576 + c*9 + kk] : 0.f;
        g_wo2[i] = __uint_as_float(tf32u(v));
    }
}

// ---------------------------------------------------------------------------
// Kernel B: offset conv via mma.sync tf32 -> (ys, xs, mask)
// Block = TWO image rows (192 px), 384 threads = 12 warps.
// Warp w: rp = w>>1 (0..5): row rp/3, px col (rp%3)*32..+31 (2 M-tiles);
//         ntp = w&1 (outputs 16*ntp..16*ntp+15).
// ---------------------------------------------------------------------------
#define B_SP_SIZE  (4*98*68)                 /* 26656 f */
#define B_SB_OFF   B_SP_SIZE
#define B_SB_SIZE  (9*8*2*32*4)              /* 18432 f */
#define B_OM_OFF   (B_SB_OFF + B_SB_SIZE)
#define B_OM_SIZE  (192*28)
#define B_SMEM_FLOATS (B_OM_OFF + B_OM_SIZE) /* 50464 f = 201.9 KB */

__global__ __launch_bounds__(384, 1) void dc_offsets(const float* __restrict__ b_off)
{
    extern __shared__ float sm[];
    float* sP  = sm;
    float* sB  = sm + B_SB_OFF;
    float* sOm = sm + B_OM_OFF;
    unsigned sbBase = (unsigned)__cvta_generic_to_shared(sB);

    int tid = threadIdx.x;
    int b   = blockIdx.x / (Hdim/2);
    int h0  = (blockIdx.x % (Hdim/2)) * 2;
    int gpixBase = b * HW + h0 * Wdim;

    for (int i = tid; i < B_SB_SIZE/4; i += 384)
        cp_async16(sbBase + (unsigned)i*16u, g_wo2 + i*4);
    cp_commit();

    // input patch: 4 rows (h0-1 .. h0+2) x 98 cols, tf32 bits, zero OOB
    const float* xtb = g_xt + (size_t)b * HW * 64;
    for (int r = 0; r < 4; r++) {
        int hh = h0 - 1 + r;
        bool rv = (hh >= 0) & (hh < Hdim);
        for (int i = tid; i < 98*64; i += 384) {
            int col = i >> 6, c = i & 63;
            int ww = col - 1;
            float v = 0.f;
            if (rv && ww >= 0 && ww < Wdim)
                v = xtb[((size_t)hh*Wdim + ww)*64 + c];
            sP[(r*98 + col)*68 + c] = __uint_as_float(tf32u(v));
        }
    }
    cp_wait0();
    __syncthreads();

    int wid  = tid >> 5, lane = tid & 31;
    int g = lane >> 2, t = lane & 3;
    int rp  = wid >> 1;            // 0..5
    int ntp = wid & 1;
    int rowsel = rp / 3;           // output row within pair
    int col0   = (rp % 3) * 32;    // px column base (2 M-tiles)

    float4 d00 = make_float4(0.f,0.f,0.f,0.f);
    float4 d01 = make_float4(0.f,0.f,0.f,0.f);
    float4 d10 = make_float4(0.f,0.f,0.f,0.f);
    float4 d11 = make_float4(0.f,0.f,0.f,0.f);
    const uint32_t* P = (const uint32_t*)sP;

    #pragma unroll
    for (int kk = 0; kk < 9; kk++) {
        int ky = kk / 3, kx = kk % 3;
        const uint32_t* arow0 = P + ((ky + rowsel)*98 + col0 + g + kx)*68;
        const uint32_t* arow1 = arow0 + 16*68;
        #pragma unroll
        for (int s = 0; s < 8; s++) {
            uint32_t a00 = arow0[s*8 + t];
            uint32_t a01 = arow0[8*68 + s*8 + t];
            uint32_t a02 = arow0[s*8 + t + 4];
            uint32_t a03 = arow0[8*68 + s*8 + t + 4];
            uint32_t a10 = arow1[s*8 + t];
            uint32_t a11 = arow1[8*68 + s*8 + t];
            uint32_t a12 = arow1[s*8 + t + 4];
            uint32_t a13 = arow1[8*68 + s*8 + t + 4];
            uint4 bq = *(const uint4*)(sB + (((kk*8 + s)*2 + ntp)*32 + lane)*4);
            mma_tf32(d00, a00,a01,a02,a03, bq.x, bq.y);
            mma_tf32(d01, a00,a01,a02,a03, bq.z, bq.w);
            mma_tf32(d10, a10,a11,a12,a13, bq.x, bq.y);
            mma_tf32(d11, a10,a11,a12,a13, bq.z, bq.w);
        }
    }

    {
        int m0 = 16*ntp + 2*t;          // d*0 -> m0, m0+1
        int m1 = 16*ntp + 8 + 2*t;      // d*1 -> m1, m1+1
        int pxW = rowsel*96 + col0 + g; // local px of Mtile0 row g
        #pragma unroll
        for (int mt = 0; mt < 2; mt++) {
            float4 dv0 = mt ? d10 : d00;
            float4 dv1 = mt ? d11 : d01;
            int pA = pxW + mt*16, pB = pA + 8;
            sOm[pA*28 + m0] = dv0.x + __ldg(&b_off[m0]);
            sOm[pB*28 + m0] = dv0.z + __ldg(&b_off[m0]);
            if (m0 + 1 < 27) {
                sOm[pA*28 + m0+1] = dv0.y + __ldg(&b_off[m0+1]);
                sOm[pB*28 + m0+1] = dv0.w + __ldg(&b_off[m0+1]);
            }
            if (m1 < 27) {
                sOm[pA*28 + m1] = dv1.x + __ldg(&b_off[m1]);
                sOm[pB*28 + m1] = dv1.z + __ldg(&b_off[m1]);
            }
            if (m1 + 1 < 27) {
                sOm[pA*28 + m1+1] = dv1.y + __ldg(&b_off[m1+1]);
                sOm[pB*28 + m1+1] = dv1.w + __ldg(&b_off[m1+1]);
            }
        }
    }
    __syncthreads();

    for (int idx = tid; idx < 192*9; idx += 384) {
        int p2 = idx / 9, k = idx % 9;
        float dy = sOm[p2*28 + 2*k];
        float dx = sOm[p2*28 + 2*k + 1];
        float mv = sOm[p2*28 + 18 + k];
        float mask = 1.0f / (1.0f + __expf(-mv));
        int ky = k / 3, kx = k % 3;
        float ys = (float)(h0 + (p2/96) - 1 + ky) + dy;
        float xs = (float)((p2%96) - 1 + kx) + dx;
        float* gp = g_pos + (size_t)(gpixBase + p2)*27 + k*3;
        gp[0] = ys; gp[1] = xs; gp[2] = mask;
    }
}

// ---------------------------------------------------------------------------
// Kernel C: fused bilinear sample + mma.sync tf32 GEMM. 2 blocks/SM.
// Block = 128 px, 256 threads = 8 warps.
// GEMM warp tile: 32 px (2 M-tiles) x 32 o: mq = wid&3 (px mq*32), oh = wid>>2.
// Gather: warp wid handles px wid*16..+15 (decoupled from GEMM tiling).
// ---------------------------------------------------------------------------
#define C_SS0    0
#define C_SS1    34816
#define C_SB0    69632
#define C_SB1    86016
#define C_COEF   102400
#define C_BASE   106496
#define C_SMEM_BYTES 108544

__global__ __launch_bounds__(256, 2)
void dc_main(const float* __restrict__ bias, float* __restrict__ out)
{
    extern __shared__ char smc[];
    unsigned smem_base = (unsigned)__cvta_generic_to_shared(smc);
    float4* sCoef = (float4*)(smc + C_COEF);   // [buf][px] buf = tap&1
    int2*   sBase = (int2*)  (smc + C_BASE);

    int tid = threadIdx.x;
    int wid = tid >> 5, lane = tid & 31;
    int g = lane >> 2, t = lane & 3;
    int b      = blockIdx.x / 72;
    int pxBase = (blockIdx.x % 72) * 128;
    int gpixBase = b * HW + pxBase;
    const float* xtb = g_xt + (size_t)b * HW * 64;
    int warpPx0 = wid * 16;          // gather mapping
    int mq = wid & 3, oh = wid >> 2; // GEMM mapping
    int px0m = mq * 32;

    float4 acc[8];   // [mt*4 + ntile], o = oh*32 + ntile*8
    #pragma unroll
    for (int a = 0; a < 8; a++) acc[a] = make_float4(0.f,0.f,0.f,0.f);

    auto meta1 = [&](int kk, int px) {
        const float* gp = g_pos + (size_t)(gpixBase + px)*27 + kk*3;
        float ys = gp[0], xs = gp[1], mk = gp[2];
        float y0f = floorf(ys), x0f = floorf(xs);
        float ty = ys - y0f, tx = xs - x0f;
        int iy0 = (int)y0f, ix0 = (int)x0f;
        float wy0 = (iy0 >= 0 && iy0 <= Hdim-1) ? (1.f - ty) : 0.f;
        float wy1 = (iy0+1 >= 0 && iy0+1 <= Hdim-1) ? ty : 0.f;
        float wx0 = (ix0 >= 0 && ix0 <= Wdim-1) ? (1.f - tx) : 0.f;
        float wx1 = (ix0+1 >= 0 && ix0+1 <= Wdim-1) ? tx : 0.f;
        int bx = min(max(ix0, 0), Wdim-1);
        float cx0 = (ix0 == bx) ? wx0 : ((ix0 + 1 == bx) ? wx1 : 0.f);
        float cx1 = (ix0 == bx) ? wx1 : 0.f;
        int cy0 = min(max(iy0,   0), Hdim-1);
        int cy1 = min(max(iy0+1, 0), Hdim-1);
        float4 cf;
        cf.x = wy0*cx0*mk;  cf.y = wy0*cx1*mk;
        cf.z = wy1*cx0*mk;  cf.w = wy1*cx1*mk;
        sCoef[(kk&1)*128 + px] = cf;
        sBase[(kk&1)*128 + px] = make_int2((cy0*Wdim + bx)*64, (cy1*Wdim + bx)*64);
    };

    // ---- prologue: B(0) cp.async; meta(0), meta(1); gather(0)
    for (int i = tid; i < 1024; i += 256)
        cp_async16(smem_base + C_SB0 + (unsigned)i*16u, g_wtm + i*4);
    cp_commit();
    {
        int kk = tid >> 7, px = tid & 127;
        meta1(kk, px);
    }
    __syncthreads();
    {
        #pragma unroll
        for (int p = 0; p < 16; p++) {
            int px = warpPx0 + p;
            int2 bs = sBase[px];
            float4 cf = sCoef[px];
            float4 q0 = *(const float4*)(xtb + bs.x + lane*4);
            float4 q1 = *(const float4*)(xtb + bs.y + lane*4);
            float c0 = (lane & 16) ? cf.y : cf.x;
            float c1 = (lane & 16) ? cf.w : cf.z;
            float t0 = q0.x*c0 + q1.x*c1;
            float t1 = q0.y*c0 + q1.y*c1;
            float t2 = q0.z*c0 + q1.z*c1;
            float t3 = q0.w*c0 + q1.w*c1;
            t0 += __shfl_xor_sync(0xffffffffu, t0, 16);
            t1 += __shfl_xor_sync(0xffffffffu, t1, 16);
            t2 += __shfl_xor_sync(0xffffffffu, t2, 16);
            t3 += __shfl_xor_sync(0xffffffffu, t3, 16);
            if (lane < 16) {
                uint32_t r0 = tf32u(t0), r1 = tf32u(t1), r2 = tf32u(t2), r3 = tf32u(t3);
                unsigned addr = smem_base + C_SS0 + (unsigned)(px*68 + lane*4)*4u;
                asm volatile("st.shared.v4.b32 [%0], {%1, %2, %3, %4};"
                             :: "r"(addr), "r"(r0), "r"(r1), "r"(r2), "r"(r3));
            }
        }
    }
    cp_wait0();
    __syncthreads();

    // ---- main loop over taps
    for (int k = 0; k < 9; k++) {
        int cur = k & 1, nxt = cur ^ 1;
        if (k < 8) {   // stream B(k+1)
            unsigned dstB = smem_base + (nxt ? C_SB1 : C_SB0);
            const float* srcB = g_wtm + (k+1)*4096;
            for (int i = tid; i < 1024; i += 256)
                cp_async16(dstB + (unsigned)i*16u, srcB + i*4);
            cp_commit();
        }
        if (k < 7 && tid < 128) meta1(k+2, tid);

        const uint32_t* ssb = (const uint32_t*)(smc + (cur ? C_SS1 : C_SS0));
        const float*    sBc = (const float*)(smc + (cur ? C_SB1 : C_SB0));
        unsigned gdst = smem_base + (nxt ? C_SS1 : C_SS0);
        const uint32_t* arow0 = ssb + (px0m + g)*68;
        const uint32_t* arow1 = arow0 + 16*68;
        const float4* cfb = sCoef + nxt*128;
        const int2*   bsb = sBase + nxt*128;

        #pragma unroll
        for (int ch = 0; ch < 8; ch++) {
            // gather(k+1) chunk: 2 px, issue LDGs early
            float4 gq0[2], gq1[2], gcf[2];
            int pg0 = warpPx0 + ch*2;
            if (k < 8) {
                #pragma unroll
                for (int p = 0; p < 2; p++) {
                    int2 bs = bsb[pg0 + p];
                    gcf[p] = cfb[pg0 + p];
                    gq0[p] = *(const float4*)(xtb + bs.x + lane*4);
                    gq1[p] = *(const float4*)(xtb + bs.y + lane*4);
                }
            }
            // GEMM: kstep s = ch; 2 M-tiles x 4 ntiles (half N)
            {
                int s = ch;
                uint32_t a00 = arow0[s*8 + t];
                uint32_t a01 = arow0[8*68 + s*8 + t];
                uint32_t a02 = arow0[s*8 + t + 4];
                uint32_t a03 = arow0[8*68 + s*8 + t + 4];
                uint32_t a10 = arow1[s*8 + t];
                uint32_t a11 = arow1[8*68 + s*8 + t];
                uint32_t a12 = arow1[s*8 + t + 4];
                uint32_t a13 = arow1[8*68 + s*8 + t + 4];
                uint4 bq0 = *(const uint4*)(sBc + ((s*4 + 2*oh    )*32 + lane)*4);
                uint4 bq1 = *(const uint4*)(sBc + ((s*4 + 2*oh + 1)*32 + lane)*4);
                mma_tf32(acc[0], a00,a01,a02,a03, bq0.x, bq0.y);
                mma_tf32(acc[1], a00,a01,a02,a03, bq0.z, bq0.w);
                mma_tf32(acc[2], a00,a01,a02,a03, bq1.x, bq1.y);
                mma_tf32(acc[3], a00,a01,a02,a03, bq1.z, bq1.w);
                mma_tf32(acc[4], a10,a11,a12,a13, bq0.x, bq0.y);
                mma_tf32(acc[5], a10,a11,a12,a13, bq0.z, bq0.w);
                mma_tf32(acc[6], a10,a11,a12,a13, bq1.x, bq1.y);
                mma_tf32(acc[7], a10,a11,a12,a13, bq1.z, bq1.w);
            }
            // gather(k+1) chunk: combine + cvt + STS
            if (k < 8) {
                #pragma unroll
                for (int p = 0; p < 2; p++) {
                    float c0 = (lane & 16) ? gcf[p].y : gcf[p].x;
                    float c1 = (lane & 16) ? gcf[p].w : gcf[p].z;
                    float t0 = gq0[p].x*c0 + gq1[p].x*c1;
                    float t1 = gq0[p].y*c0 + gq1[p].y*c1;
                    float t2 = gq0[p].z*c0 + gq1[p].z*c1;
                    float t3 = gq0[p].w*c0 + gq1[p].w*c1;
                    t0 += __shfl_xor_sync(0xffffffffu, t0, 16);
                    t1 += __shfl_xor_sync(0xffffffffu, t1, 16);
                    t2 += __shfl_xor_sync(0xffffffffu, t2, 16);
                    t3 += __shfl_xor_sync(0xffffffffu, t3, 16);
                    if (lane < 16) {
                        uint32_t r0 = tf32u(t0), r1 = tf32u(t1),
                                 r2 = tf32u(t2), r3 = tf32u(t3);
                        unsigned addr = gdst + (unsigned)((pg0+p)*68 + lane*4)*4u;
                        asm volatile("st.shared.v4.b32 [%0], {%1, %2, %3, %4};"
                                     :: "r"(addr), "r"(r0), "r"(r1), "r"(r2), "r"(r3));
                    }
                }
            }
        }
        cp_wait0();
        __syncthreads();
    }

    // ---- epilogue: fragments -> sOut[o][px] (stride 132), then NCHW store
    float* sOut = (float*)smc;
    #pragma unroll
    for (int mt = 0; mt < 2; mt++)
        #pragma unroll
        for (int nt = 0; nt < 4; nt++) {
            float4 dv = acc[mt*4 + nt];
            int o = oh*32 + nt*8 + 2*t;
            int pA = px0m + mt*16 + g, pB = pA + 8;
            sOut[o*132 + pA]     = dv.x;
            sOut[(o+1)*132 + pA] = dv.y;
            sOut[o*132 + pB]     = dv.z;
            sOut[(o+1)*132 + pB] = dv.w;
        }
    __syncthreads();
    float* ob = out + (size_t)b * COUT * HW + pxBase;
    for (int i = tid; i < 64*128; i += 256) {
        int o = i >> 7, p = i & 127;
        ob[(size_t)o*HW + p] = sOut[o*132 + p] + __ldg(&bias[o]);
    }
}

// ---------------------------------------------------------------------------
extern "C" void kernel_launch(void* const* d_in, const int* in_sizes, int n_in,
                              void* d_out, int out_size)
{
    const float* x      = (const float*)d_in[0];
    const float* w_off  = (const float*)d_in[1];
    const float* b_off  = (const float*)d_in[2];
    const float* weight = (const float*)d_in[3];
    const float* bias   = (const float*)d_in[4];
    float* out = (float*)d_out;

    static bool attr_done = false;
    if (!attr_done) {
        cudaFuncSetAttribute(dc_offsets, cudaFuncAttributeMaxDynamicSharedMemorySize,
                             B_SMEM_FLOATS * (int)sizeof(float));
        cudaFuncSetAttribute(dc_main, cudaFuncAttributeMaxDynamicSharedMemorySize,
                             C_SMEM_BYTES);
        attr_done = true;
    }

    dc_transpose<<<Bdim * (HW/64), 256>>>(x);
    dc_wtrans   <<<(9*64*64 + 255)/256, 256>>>(weight, w_off);
    dc_offsets  <<<Bdim * (Hdim/2), 384, B_SMEM_FLOATS * sizeof(float)>>>(b_off);
    dc_main     <<<Bdim * 72, 256, C_SMEM_BYTES>>>(bias, out);
}